// round 13
// baseline (speedup 1.0000x reference)
#include <cuda_runtime.h>
#include <cuda_fp16.h>
#include <cstdint>
#include <cstddef>

#define BATCH  2
#define SEQ    2048
#define DMODEL 1024
#define NHEAD  16
#define DHEAD  64
#define BH     (BATCH*NHEAD)
#define MROWS  (BATCH*SEQ)
#define SCALE  0.022097086912079608f   // 1/sqrt(2048)

// ---------------- scratch (device globals; allocation-free rule) -----------
__device__ __align__(16) __half g_Xh[(size_t)3 * MROWS * DMODEL];    // fp16 q/k/v inputs
__device__ __align__(16) __half g_Wth[(size_t)3 * DMODEL * DMODEL];  // fp16 n-major WQ/WK/WV
__device__ __align__(16) __half g_WOth[(size_t)DMODEL * DMODEL];     // fp16 n-major WO
__device__ __align__(16) __half g_Qh[(size_t)BH * SEQ * DHEAD];
__device__ __align__(16) __half g_Kh[(size_t)BH * SEQ * DHEAD];
__device__ __align__(16) __half g_Vh[(size_t)BH * SEQ * DHEAD];
__device__ __align__(16) __half g_Vt[(size_t)BH * DHEAD * SEQ];      // [bh][e][k], scaled 1/den
__device__ __align__(16) __half g_Ph[(size_t)BH * SEQ * SEQ];        // exp(scores) fp16
__device__ __align__(16) __half g_Ocat[(size_t)MROWS * DMODEL];      // fp16 attention output

// ---------------- helpers ---------------------------------------------------
__device__ __forceinline__ uint32_t swz(uint32_t o) { return o ^ ((o >> 3) & 0x70); }
__device__ __forceinline__ uint32_t smem_u32(const void* p) {
    return (uint32_t)__cvta_generic_to_shared(p);
}
__device__ __forceinline__ void cp16a(uint32_t saddr, const void* gmem) {
    asm volatile("cp.async.cg.shared.global [%0], [%1], 16;" :: "r"(saddr), "l"(gmem));
}
__device__ __forceinline__ void cp_commit() { asm volatile("cp.async.commit_group;"); }
template <int N> __device__ __forceinline__ void cp_wait() {
    asm volatile("cp.async.wait_group %0;" :: "n"(N));
}
__device__ __forceinline__ void ldsm4(uint32_t (&r)[4], uint32_t saddr) {
    asm volatile("ldmatrix.sync.aligned.m8n8.x4.shared.b16 {%0,%1,%2,%3}, [%4];"
                 : "=r"(r[0]), "=r"(r[1]), "=r"(r[2]), "=r"(r[3]) : "r"(saddr));
}
__device__ __forceinline__ void mma16h(float (&c)[4], const uint32_t (&a)[4], const uint32_t* b) {
    asm volatile(
        "mma.sync.aligned.m16n8k16.row.col.f32.f16.f16.f32 "
        "{%0,%1,%2,%3}, {%4,%5,%6,%7}, {%8,%9}, {%0,%1,%2,%3};"
        : "+f"(c[0]), "+f"(c[1]), "+f"(c[2]), "+f"(c[3])
        : "r"(a[0]), "r"(a[1]), "r"(a[2]), "r"(a[3]), "r"(b[0]), "r"(b[1]));
}
#define LANE_OFFS() \
    int lane = threadIdx.x & 31; \
    int aRow = ((lane >> 3) & 1) * 8 + (lane & 7); \
    int aK16 = (lane >> 4) * 16; \
    int bRow = (lane >> 4) * 8 + (lane & 7); \
    int bK16 = ((lane >> 3) & 1) * 16; \
    int gg = lane >> 2, tt = lane & 3; (void)gg; (void)tt;

// ---------------------------------------------------------------------------
// Prologue: queries/keys/values -> fp16
// ---------------------------------------------------------------------------
__global__ __launch_bounds__(256) void xprep_kernel(const float4* __restrict__ q,
                                                    const float4* __restrict__ k,
                                                    const float4* __restrict__ v) {
    int which = blockIdx.z;
    const float4* src = (which == 0) ? q : (which == 1) ? k : v;
    size_t i = (size_t)blockIdx.x * 256 + threadIdx.x;
    float4 x = src[i];
    __half* dst = g_Xh + (size_t)which * MROWS * DMODEL + i * 4;
    *(__half2*)dst = __floats2half2_rn(x.x, x.y);
    *(__half2*)(dst + 2) = __floats2half2_rn(x.z, x.w);
}

// z<3: W[h][d][e] -> fp16 n-major [h*64+e][d]; z==3: WO[d][c] -> fp16 [c][d]
__global__ __launch_bounds__(256) void wprep_kernel(const float* __restrict__ WQ,
                                                    const float* __restrict__ WK,
                                                    const float* __restrict__ WV,
                                                    const float* __restrict__ WO) {
    int which = blockIdx.z;
    __shared__ float tile[64 * 65];
    int t = threadIdx.x;
    if (which < 3) {
        int h = blockIdx.y, d0 = blockIdx.x * 64;
        const float* W = ((which == 0) ? WQ : (which == 1) ? WK : WV)
                         + ((size_t)h * DMODEL + d0) * DHEAD;
#pragma unroll
        for (int j = 0; j < 16; j++) {
            int u = t + j * 256;
            tile[(u >> 6) * 65 + (u & 63)] = W[(size_t)(u >> 6) * DHEAD + (u & 63)];
        }
        __syncthreads();
        __half* out = g_Wth + (size_t)which * DMODEL * DMODEL + (size_t)h * 64 * DMODEL + d0;
#pragma unroll
        for (int j = 0; j < 16; j++) {
            int u = t + j * 256;
            int e = u >> 6, dc = u & 63;
            out[(size_t)e * DMODEL + dc] = __float2half_rn(tile[dc * 65 + e]);
        }
    } else {
        int d0 = blockIdx.x * 64, c0 = blockIdx.y * 64;
#pragma unroll
        for (int j = 0; j < 16; j++) {
            int u = t + j * 256;
            tile[(u >> 6) * 65 + (u & 63)] = WO[(size_t)(d0 + (u >> 6)) * DMODEL + c0 + (u & 63)];
        }
        __syncthreads();
#pragma unroll
        for (int j = 0; j < 16; j++) {
            int u = t + j * 256;
            int cr = u >> 6, dc = u & 63;
            g_WOth[(size_t)(c0 + cr) * DMODEL + d0 + dc] = __float2half_rn(tile[dc * 65 + cr]);
        }
    }
}

// ---------------------------------------------------------------------------
// proj_kernel: all three projections, fp16, BM=64 x BN=128 tiles (fine-grain
// wave packing), 8 warps as 2x4 -> warp 32x32, BK=64, 3-stage, occupancy 3.
// z=0 -> g_Qh, z=1 -> g_Kh, z=2 -> g_Vh.
// ---------------------------------------------------------------------------
__global__ __launch_bounds__(256, 3) void proj_kernel() {
    extern __shared__ float smf[];
    uint32_t sA = smem_u32(smf);           // [3][64 x 128B]  = 24KB
    uint32_t sB = sA + 3 * 8192;           // [3][128 x 128B] = 48KB

    int t = threadIdx.x, wid = t >> 5;
    int wm = wid & 1, wn = wid >> 1;       // 2x4 warps -> 64x128, warp 32x32
    int m0 = blockIdx.x * 64, n0 = blockIdx.y * 128, which = blockIdx.z;
    LANE_OFFS();

    const __half* A = g_Xh + (size_t)which * MROWS * DMODEL + (size_t)m0 * DMODEL;
    const __half* B = g_Wth + (size_t)which * DMODEL * DMODEL + (size_t)n0 * DMODEL;

    uint32_t aOffU = (uint32_t)(wm * 32 + aRow) * 128 + aK16;
    uint32_t bOffU = (uint32_t)(wn * 32 + bRow) * 128 + bK16;

    float acc[2][4][4];
#pragma unroll
    for (int mi = 0; mi < 2; mi++)
#pragma unroll
        for (int nj = 0; nj < 4; nj++)
#pragma unroll
            for (int e = 0; e < 4; e++) acc[mi][nj][e] = 0.0f;

    auto issue = [&](int it3) {
        int s = it3 % 3;
        int kk = it3 * 64;
        uint32_t bA = sA + s * 8192;
        uint32_t bB = sB + s * 16384;
#pragma unroll
        for (int j = 0; j < 2; j++) {          // A: 64 rows x 128B
            int u = t + j * 256;
            int row = u >> 3, ch = u & 7;
            cp16a(bA + swz(row * 128 + ch * 16), A + (size_t)row * DMODEL + kk + ch * 8);
        }
#pragma unroll
        for (int j = 0; j < 4; j++) {          // B: 128 rows x 128B
            int u = t + j * 256;
            int row = u >> 3, ch = u & 7;
            cp16a(bB + swz(row * 128 + ch * 16), B + (size_t)row * DMODEL + kk + ch * 8);
        }
    };

    issue(0); cp_commit();
    issue(1); cp_commit();
#pragma unroll 1
    for (int it = 0; it < 16; it++) {
        if (it < 15) cp_wait<1>(); else cp_wait<0>();
        __syncthreads();
        uint32_t bA = sA + (it % 3) * 8192;
        uint32_t bB = sB + (it % 3) * 16384;
#pragma unroll
        for (int slab = 0; slab < 4; slab++) {
            uint32_t a[2][4], b[2][4];
            ldsm4(a[0], bA + swz(aOffU + slab * 32));
            ldsm4(a[1], bA + swz(aOffU + 2048 + slab * 32));
            ldsm4(b[0], bB + swz(bOffU + slab * 32));
            ldsm4(b[1], bB + swz(bOffU + 2048 + slab * 32));
#pragma unroll
            for (int mi = 0; mi < 2; mi++)
#pragma unroll
                for (int nj = 0; nj < 4; nj++)
                    mma16h(acc[mi][nj], a[mi], &b[nj >> 1][(nj & 1) * 2]);
        }
        if (it + 2 < 16) { issue(it + 2); cp_commit(); }
    }

    __half* Outp = (which == 0) ? g_Qh : (which == 1) ? g_Kh : g_Vh;
#pragma unroll
    for (int mi = 0; mi < 2; mi++) {
        int mrow = m0 + wm * 32 + mi * 16 + gg;
#pragma unroll
        for (int nj = 0; nj < 4; nj++) {
            int col = n0 + wn * 32 + nj * 8 + 2 * tt;
            int b = mrow >> 11, s = mrow & (SEQ - 1);
            int h = col >> 6, e = col & 63;
            __half* dst = Outp + ((size_t)(b * NHEAD + h) * SEQ + s) * DHEAD + e;
            *(__half2*)dst = __floats2half2_rn(acc[mi][nj][0], acc[mi][nj][1]);
            *(__half2*)(dst + 8 * DHEAD) = __floats2half2_rn(acc[mi][nj][2], acc[mi][nj][3]);
        }
    }
}

// ---------------------------------------------------------------------------
// out_kernel (fp16, 128x128, BK=64, 3-stage, single-sync): Out = Ocat @ WOt^T.
// ---------------------------------------------------------------------------
__global__ __launch_bounds__(256, 2) void out_kernel(float* __restrict__ Cout) {
    extern __shared__ float smf[];
    uint32_t sA = smem_u32(smf);
    uint32_t sB = sA + 3 * 16384;

    int t = threadIdx.x, wid = t >> 5;
    int wm = wid & 1, wn = wid >> 1;
    int m0 = blockIdx.x * 128, n0 = blockIdx.y * 128;
    LANE_OFFS();

    const __half* A = g_Ocat + (size_t)m0 * DMODEL;
    const __half* B = g_WOth + (size_t)n0 * DMODEL;

    float acc[4][4][4];
#pragma unroll
    for (int mi = 0; mi < 4; mi++)
#pragma unroll
        for (int nj = 0; nj < 4; nj++)
#pragma unroll
            for (int e = 0; e < 4; e++) acc[mi][nj][e] = 0.0f;

    auto issue = [&](int it3) {
        int s = it3 % 3;
        int kk = it3 * 64;
        uint32_t bA = sA + s * 16384;
        uint32_t bB = sB + s * 16384;
#pragma unroll
        for (int j = 0; j < 4; j++) {
            int u = t + j * 256;
            int row = u >> 3, ch = u & 7;
            uint32_t off = swz(row * 128 + ch * 16);
            cp16a(bA + off, A + (size_t)row * DMODEL + kk + ch * 8);
            cp16a(bB + off, B + (size_t)row * DMODEL + kk + ch * 8);
        }
    };

    uint32_t aOffU = (uint32_t)(wm * 64 + aRow) * 128 + aK16;
    uint32_t bOffU = (uint32_t)(wn * 32 + bRow) * 128 + bK16;

    issue(0); cp_commit();
    issue(1); cp_commit();
#pragma unroll 1
    for (int it = 0; it < 16; it++) {
        if (it < 15) cp_wait<1>(); else cp_wait<0>();
        __syncthreads();
        uint32_t bA = sA + (it % 3) * 16384;
        uint32_t bB = sB + (it % 3) * 16384;
#pragma unroll
        for (int slab = 0; slab < 4; slab++) {
            uint32_t a[4][4], b[2][4];
#pragma unroll
            for (int mi = 0; mi < 4; mi++)
                ldsm4(a[mi], bA + swz(aOffU + mi * 2048 + slab * 32));
#pragma unroll
            for (int g2 = 0; g2 < 2; g2++)
                ldsm4(b[g2], bB + swz(bOffU + g2 * 2048 + slab * 32));
#pragma unroll
            for (int mi = 0; mi < 4; mi++)
#pragma unroll
                for (int nj = 0; nj < 4; nj++)
                    mma16h(acc[mi][nj], a[mi], &b[nj >> 1][(nj & 1) * 2]);
        }
        if (it + 2 < 16) { issue(it + 2); cp_commit(); }
    }

#pragma unroll
    for (int mi = 0; mi < 4; mi++) {
        int mrow = m0 + wm * 64 + mi * 16 + gg;
#pragma unroll
        for (int nj = 0; nj < 4; nj++) {
            int col = n0 + wn * 32 + nj * 8 + 2 * tt;
            float* d0 = Cout + (size_t)mrow * DMODEL + col;
            *(float2*)d0 = make_float2(acc[mi][nj][0], acc[mi][nj][1]);
            *(float2*)(d0 + 8 * DMODEL) = make_float2(acc[mi][nj][2], acc[mi][nj][3]);
        }
    }
}

// ---------------------------------------------------------------------------
// den_kernel v2: per (128-wide k-stripe kt, bh), 64-row q tiles:
//   S = Q K^T (Q double-buffered 8KB tiles), P = exp(...) -> g_Ph fp16
//   (LOCAL column index); colsums in registers; V stripe (128 rows) scaled
//   by 1/den and transposed into g_Vt. Halves Q traffic vs 64-wide stripes.
// ---------------------------------------------------------------------------
__global__ __launch_bounds__(256, 2) void den_kernel() {
    int kt = blockIdx.x;          // 0..15, heavy first
    int bh = blockIdx.y;

    extern __shared__ float smf[];
    uint32_t sK = smem_u32(smf);                 // K stripe: 128 rows = 16KB
    uint32_t sQ = sK + 16384;                    // Q tiles: 2 x 8KB
    __half* Vstage = (__half*)((char*)smf + 16384 + 16384);  // [128][66] fp16
    __shared__ float colsum[2][128];
    __shared__ float invs[128];

    int t = threadIdx.x, wid = t >> 5;
    int wm = wid & 1, wn = wid >> 1;             // 2x4 warps -> 64q x 128k
    LANE_OFFS();

    const __half* Qg = g_Qh + (size_t)bh * SEQ * DHEAD;
    const __half* Kg = g_Kh + ((size_t)bh * SEQ + kt * 128) * DHEAD;
    __half* Pb = g_Ph + (size_t)bh * SEQ * SEQ + kt * 128;

    auto issueQ = [&](int qt, int s) {
        const __half* src = Qg + (size_t)qt * 64 * DHEAD;
        uint32_t base = sQ + s * 8192;
#pragma unroll
        for (int j = 0; j < 2; j++) {            // 64 rows x 128B
            int u = t + j * 256;
            int row = u >> 3, ch = u & 7;
            cp16a(base + swz(row * 128 + ch * 16), src + (size_t)row * DHEAD + ch * 8);
        }
    };

#pragma unroll
    for (int j = 0; j < 4; j++) {                // K: 128 rows x 128B
        int u = t + j * 256;
        int row = u >> 3, ch = u & 7;
        cp16a(sK + swz(row * 128 + ch * 16), Kg + (size_t)row * DHEAD + ch * 8);
    }
    int qt0 = kt * 2;
    issueQ(qt0, 0); cp_commit(); cp_wait<0>(); __syncthreads();

    uint32_t aOffU = (uint32_t)(wm * 32 + aRow) * 128 + aK16;
    uint32_t bOffU = (uint32_t)(wn * 32 + bRow) * 128 + bK16;

    float part[4][2];
#pragma unroll
    for (int nj = 0; nj < 4; nj++) { part[nj][0] = 0.0f; part[nj][1] = 0.0f; }

#pragma unroll 1
    for (int qt = qt0; qt < SEQ / 64; qt++) {
        int it = qt - qt0;
        if (qt + 1 < SEQ / 64) { issueQ(qt + 1, (it + 1) & 1); cp_commit(); }

        uint32_t baQ = sQ + (it & 1) * 8192;
        float acc[2][4][4];
#pragma unroll
        for (int mi = 0; mi < 2; mi++)
#pragma unroll
            for (int nj = 0; nj < 4; nj++)
#pragma unroll
                for (int e = 0; e < 4; e++) acc[mi][nj][e] = 0.0f;

#pragma unroll
        for (int slab = 0; slab < 4; slab++) {
            uint32_t a[2][4], b[2][4];
            ldsm4(a[0], baQ + swz(aOffU + slab * 32));
            ldsm4(a[1], baQ + swz(aOffU + 2048 + slab * 32));
            ldsm4(b[0], sK + swz(bOffU + slab * 32));
            ldsm4(b[1], sK + swz(bOffU + 2048 + slab * 32));
#pragma unroll
            for (int mi = 0; mi < 2; mi++)
#pragma unroll
                for (int nj = 0; nj < 4; nj++)
                    mma16h(acc[mi][nj], a[mi], &b[nj >> 1][(nj & 1) * 2]);
        }

        int q0 = qt * 64;
#pragma unroll
        for (int mi = 0; mi < 2; mi++) {
            int row = wm * 32 + mi * 16 + gg;
            int q = q0 + row;
#pragma unroll
            for (int nj = 0; nj < 4; nj++) {
                int kl = wn * 32 + nj * 8 + 2 * tt;   // local column 0..127
                int kg = kt * 128 + kl;               // global k (mask/bias only)
                float v0 = (kg     <= q) ? __expf((acc[mi][nj][0] + (float)(kg - q)) * SCALE) : 0.0f;
                float v1 = (kg + 1 <= q) ? __expf((acc[mi][nj][1] + (float)(kg + 1 - q)) * SCALE) : 0.0f;
                float v2 = (kg     <= q + 8) ? __expf((acc[mi][nj][2] + (float)(kg - q - 8)) * SCALE) : 0.0f;
                float v3 = (kg + 1 <= q + 8) ? __expf((acc[mi][nj][3] + (float)(kg + 1 - q - 8)) * SCALE) : 0.0f;
                part[nj][0] += v0 + v2;
                part[nj][1] += v1 + v3;
                *(__half2*)&Pb[(size_t)q * SEQ + kl] = __floats2half2_rn(v0, v1);
                *(__half2*)&Pb[(size_t)(q + 8) * SEQ + kl] = __floats2half2_rn(v2, v3);
            }
        }
        cp_wait<0>(); __syncthreads();
    }

    // column-sum reduction: butterfly across gg groups, then across wm warps
#pragma unroll
    for (int nj = 0; nj < 4; nj++)
#pragma unroll
        for (int p = 0; p < 2; p++) {
            float v = part[nj][p];
            v += __shfl_xor_sync(0xffffffffu, v, 4);
            v += __shfl_xor_sync(0xffffffffu, v, 8);
            v += __shfl_xor_sync(0xffffffffu, v, 16);
            part[nj][p] = v;
        }
    if (lane < 4) {
#pragma unroll
        for (int nj = 0; nj < 4; nj++) {
            colsum[wm][wn * 32 + nj * 8 + 2 * lane]     = part[nj][0];
            colsum[wm][wn * 32 + nj * 8 + 2 * lane + 1] = part[nj][1];
        }
    }
    __syncthreads();
    if (t < 128)
        invs[t] = 1.0f / (colsum[0][t] + colsum[1][t]);
    __syncthreads();

    // scale + transpose fp16 V stripe (128 k-rows) -> g_Vt  (pitch 66: conflict-free)
    const __half* Vg = g_Vh + ((size_t)bh * SEQ + kt * 128) * DHEAD;
#pragma unroll
    for (int j = 0; j < 4; j++) {
        int u = t + j * 256;                 // 1024 x 16B covers 128x64 halves
        int r = u >> 3, e8 = (u & 7) * 8;
        uint4 raw = *(const uint4*)&Vg[(size_t)r * DHEAD + e8];
        float iv = invs[r];
        __half2 h0 = *(__half2*)&raw.x, h1 = *(__half2*)&raw.y;
        __half2 h2 = *(__half2*)&raw.z, h3 = *(__half2*)&raw.w;
        Vstage[r * 66 + e8 + 0] = __float2half_rn(__low2float(h0) * iv);
        Vstage[r * 66 + e8 + 1] = __float2half_rn(__high2float(h0) * iv);
        Vstage[r * 66 + e8 + 2] = __float2half_rn(__low2float(h1) * iv);
        Vstage[r * 66 + e8 + 3] = __float2half_rn(__high2float(h1) * iv);
        Vstage[r * 66 + e8 + 4] = __float2half_rn(__low2float(h2) * iv);
        Vstage[r * 66 + e8 + 5] = __float2half_rn(__high2float(h2) * iv);
        Vstage[r * 66 + e8 + 6] = __float2half_rn(__low2float(h3) * iv);
        Vstage[r * 66 + e8 + 7] = __float2half_rn(__high2float(h3) * iv);
    }
    __syncthreads();
    __half* Vt = g_Vt + (size_t)bh * DHEAD * SEQ + kt * 128;
#pragma unroll
    for (int er = 0; er < 8; er++) {
        int e = wid * 8 + er;
#pragma unroll
        for (int half_ = 0; half_ < 4; half_++) {
            int r = lane + half_ * 32;
            Vt[(size_t)e * SEQ + r] = Vstage[r * 66 + e];
        }
    }
}

// ---------------------------------------------------------------------------
// pv_kernel (fp16): Ocat[128q x 64e] = P @ Vt^T, BK=64, 3-stage, occupancy 3.
// ---------------------------------------------------------------------------
__global__ __launch_bounds__(256, 3) void pv_kernel() {
    int qt = (int)gridDim.x - 1 - blockIdx.x;
    int bh = blockIdx.y;
    int b = bh >> 4, h = bh & 15;

    extern __shared__ float smf[];
    uint32_t sP = smem_u32(smf);                 // [3][128 x 128B] = 48KB
    uint32_t sV = sP + 3 * 16384;                // [3][64 x 128B]  = 24KB

    int t = threadIdx.x, wid = t >> 5;
    int wm = wid & 3, wn = wid >> 2;
    LANE_OFFS();

    const __half* Pg = g_Ph + ((size_t)bh * SEQ + qt * 128) * SEQ;
    const __half* Vtg = g_Vt + (size_t)bh * DHEAD * SEQ;

    float acc[2][4][4];
#pragma unroll
    for (int mi = 0; mi < 2; mi++)
#pragma unroll
        for (int nj = 0; nj < 4; nj++)
#pragma unroll
            for (int e = 0; e < 4; e++) acc[mi][nj][e] = 0.0f;

    int niter = 2 * qt + 2;

    auto issue = [&](int it3) {
        int s = it3 % 3;
        uint32_t bP = sP + s * 16384;
#pragma unroll
        for (int j = 0; j < 4; j++) {
            int u = t + j * 256;
            int row = u >> 3, ch = u & 7;
            cp16a(bP + swz(row * 128 + ch * 16), Pg + (size_t)row * SEQ + it3 * 64 + ch * 8);
        }
        uint32_t bV = sV + s * 8192;
#pragma unroll
        for (int j = 0; j < 2; j++) {
            int u = t + j * 256;
            int row = u >> 3, ch = u & 7;
            cp16a(bV + swz(row * 128 + ch * 16), Vtg + (size_t)row * SEQ + it3 * 64 + ch * 8);
        }
    };

    uint32_t aOffU = (uint32_t)(wm * 32 + aRow) * 128 + aK16;
    uint32_t bOffU = (uint32_t)(wn * 32 + bRow) * 128 + bK16;

    issue(0); cp_commit();
    if (niter > 1) { issue(1); cp_commit(); }
#pragma unroll 1
    for (int it = 0; it < niter; it++) {
        if (it + 1 < niter) cp_wait<1>(); else cp_wait<0>();
        __syncthreads();
        uint32_t bP = sP + (it % 3) * 16384;
        uint32_t bV = sV + (it % 3) * 8192;
#pragma unroll
        for (int slab = 0; slab < 4; slab++) {
            uint32_t a[2][4], bfr[2][4];
            ldsm4(a[0], bP + swz(aOffU + slab * 32));
            ldsm4(a[1], bP + swz(aOffU + 2048 + slab * 32));
            ldsm4(bfr[0], bV + swz(bOffU + slab * 32));
            ldsm4(bfr[1], bV + swz(bOffU + 2048 + slab * 32));
#pragma unroll
            for (int mi = 0; mi < 2; mi++)
#pragma unroll
                for (int nj = 0; nj < 4; nj++)
                    mma16h(acc[mi][nj], a[mi], &bfr[nj >> 1][(nj & 1) * 2]);
        }
        if (it + 2 < niter) { issue(it + 2); cp_commit(); }
    }

#pragma unroll
    for (int mi = 0; mi < 2; mi++) {
        int row = qt * 128 + wm * 32 + mi * 16 + gg;
#pragma unroll
        for (int nj = 0; nj < 4; nj++) {
            int colL = wn * 32 + nj * 8 + 2 * tt;
            __half* d0 = g_Ocat + ((size_t)(b * SEQ) + row) * DMODEL + h * 64 + colL;
            *(__half2*)d0 = __floats2half2_rn(acc[mi][nj][0], acc[mi][nj][1]);
            *(__half2*)(d0 + 8 * DMODEL) = __floats2half2_rn(acc[mi][nj][2], acc[mi][nj][3]);
        }
    }
}

// ---------------------------------------------------------------------------
// Launch. Inputs: keys, queries, values, WQ, WK, WV, WO, masking
// ---------------------------------------------------------------------------
extern "C" void kernel_launch(void* const* d_in, const int* in_sizes, int n_in,
                              void* d_out, int out_size) {
    const float* keys    = (const float*)d_in[0];
    const float* queries = (const float*)d_in[1];
    const float* values  = (const float*)d_in[2];
    const float* WQ      = (const float*)d_in[3];
    const float* WK      = (const float*)d_in[4];
    const float* WV      = (const float*)d_in[5];
    const float* WO      = (const float*)d_in[6];
    float* out = (float*)d_out;
    (void)in_sizes; (void)n_in; (void)out_size;

    const int projSmem = 3 * 8192 + 3 * 16384;                // 73728
    const int outSmem  = 3 * 16384 * 2;                       // 98304
    const int denSmem  = 16384 + 16384 + 128 * 66 * 2;        // 49664
    const int pvSmem   = 3 * 16384 + 3 * 8192;                // 73728
    cudaFuncSetAttribute(proj_kernel, cudaFuncAttributeMaxDynamicSharedMemorySize, projSmem);
    cudaFuncSetAttribute(out_kernel,  cudaFuncAttributeMaxDynamicSharedMemorySize, outSmem);
    cudaFuncSetAttribute(den_kernel,  cudaFuncAttributeMaxDynamicSharedMemorySize, denSmem);
    cudaFuncSetAttribute(pv_kernel,   cudaFuncAttributeMaxDynamicSharedMemorySize, pvSmem);

    // prologue (all fp16)
    xprep_kernel<<<dim3(MROWS * DMODEL / 4 / 256, 1, 3), 256>>>(
        (const float4*)queries, (const float4*)keys, (const float4*)values);
    wprep_kernel<<<dim3(DMODEL / 64, 16, 4), 256>>>(WQ, WK, WV, WO);

    // projections, fine-grain tiles (z=0 Q, z=1 K, z=2 V)
    proj_kernel<<<dim3(MROWS / 64, DMODEL / 128, 3), 256, projSmem>>>();

    // attention (fp16)
    den_kernel<<<dim3(SEQ / 128, BH), 256, denSmem>>>();
    pv_kernel<<<dim3(SEQ / 128, BH), 256, pvSmem>>>();

    // output projection (fp16)
    out_kernel<<<dim3(MROWS / 128, DMODEL / 128), 256, outSmem>>>(out);
}

// round 14
// speedup vs baseline: 1.0656x; 1.0656x over previous
#include <cuda_runtime.h>
#include <cuda_fp16.h>
#include <cstdint>
#include <cstddef>

#define BATCH  2
#define SEQ    2048
#define DMODEL 1024
#define NHEAD  16
#define DHEAD  64
#define BH     (BATCH*NHEAD)
#define MROWS  (BATCH*SEQ)
#define SCALE  0.022097086912079608f   // 1/sqrt(2048)

// ---------------- scratch (device globals; allocation-free rule) -----------
__device__ __align__(16) __half g_Xh[(size_t)3 * MROWS * DMODEL];    // fp16 q/k/v inputs
__device__ __align__(16) __half g_Wth[(size_t)3 * DMODEL * DMODEL];  // fp16 n-major WQ/WK/WV
__device__ __align__(16) __half g_WOth[(size_t)DMODEL * DMODEL];     // fp16 n-major WO
__device__ __align__(16) __half g_Qh[(size_t)BH * SEQ * DHEAD];
__device__ __align__(16) __half g_Kh[(size_t)BH * SEQ * DHEAD];
__device__ __align__(16) __half g_Vh[(size_t)BH * SEQ * DHEAD];
__device__ __align__(16) __half g_Vt[(size_t)BH * DHEAD * SEQ];      // [bh][e][k], scaled 1/den
__device__ __align__(16) __half g_Ph[(size_t)BH * SEQ * SEQ];        // exp(scores) fp16
__device__ __align__(16) __half g_Ocat[(size_t)MROWS * DMODEL];      // fp16 attention output

// ---------------- helpers ---------------------------------------------------
__device__ __forceinline__ uint32_t swz(uint32_t o) { return o ^ ((o >> 3) & 0x70); }
__device__ __forceinline__ uint32_t smem_u32(const void* p) {
    return (uint32_t)__cvta_generic_to_shared(p);
}
__device__ __forceinline__ void cp16a(uint32_t saddr, const void* gmem) {
    asm volatile("cp.async.cg.shared.global [%0], [%1], 16;" :: "r"(saddr), "l"(gmem));
}
__device__ __forceinline__ void cp_commit() { asm volatile("cp.async.commit_group;"); }
template <int N> __device__ __forceinline__ void cp_wait() {
    asm volatile("cp.async.wait_group %0;" :: "n"(N));
}
__device__ __forceinline__ void ldsm4(uint32_t (&r)[4], uint32_t saddr) {
    asm volatile("ldmatrix.sync.aligned.m8n8.x4.shared.b16 {%0,%1,%2,%3}, [%4];"
                 : "=r"(r[0]), "=r"(r[1]), "=r"(r[2]), "=r"(r[3]) : "r"(saddr));
}
__device__ __forceinline__ void mma16h(float (&c)[4], const uint32_t (&a)[4], const uint32_t* b) {
    asm volatile(
        "mma.sync.aligned.m16n8k16.row.col.f32.f16.f16.f32 "
        "{%0,%1,%2,%3}, {%4,%5,%6,%7}, {%8,%9}, {%0,%1,%2,%3};"
        : "+f"(c[0]), "+f"(c[1]), "+f"(c[2]), "+f"(c[3])
        : "r"(a[0]), "r"(a[1]), "r"(a[2]), "r"(a[3]), "r"(b[0]), "r"(b[1]));
}
#define LANE_OFFS() \
    int lane = threadIdx.x & 31; \
    int aRow = ((lane >> 3) & 1) * 8 + (lane & 7); \
    int aK16 = (lane >> 4) * 16; \
    int bRow = (lane >> 4) * 8 + (lane & 7); \
    int bK16 = ((lane >> 3) & 1) * 16; \
    int gg = lane >> 2, tt = lane & 3; (void)gg; (void)tt;

// ---------------------------------------------------------------------------
// Prologue: queries/keys/values -> fp16
// ---------------------------------------------------------------------------
__global__ __launch_bounds__(256) void xprep_kernel(const float4* __restrict__ q,
                                                    const float4* __restrict__ k,
                                                    const float4* __restrict__ v) {
    int which = blockIdx.z;
    const float4* src = (which == 0) ? q : (which == 1) ? k : v;
    size_t i = (size_t)blockIdx.x * 256 + threadIdx.x;
    float4 x = src[i];
    __half* dst = g_Xh + (size_t)which * MROWS * DMODEL + i * 4;
    *(__half2*)dst = __floats2half2_rn(x.x, x.y);
    *(__half2*)(dst + 2) = __floats2half2_rn(x.z, x.w);
}

// z<3: W[h][d][e] -> fp16 n-major [h*64+e][d]; z==3: WO[d][c] -> fp16 [c][d]
__global__ __launch_bounds__(256) void wprep_kernel(const float* __restrict__ WQ,
                                                    const float* __restrict__ WK,
                                                    const float* __restrict__ WV,
                                                    const float* __restrict__ WO) {
    int which = blockIdx.z;
    __shared__ float tile[64 * 65];
    int t = threadIdx.x;
    if (which < 3) {
        int h = blockIdx.y, d0 = blockIdx.x * 64;
        const float* W = ((which == 0) ? WQ : (which == 1) ? WK : WV)
                         + ((size_t)h * DMODEL + d0) * DHEAD;
#pragma unroll
        for (int j = 0; j < 16; j++) {
            int u = t + j * 256;
            tile[(u >> 6) * 65 + (u & 63)] = W[(size_t)(u >> 6) * DHEAD + (u & 63)];
        }
        __syncthreads();
        __half* out = g_Wth + (size_t)which * DMODEL * DMODEL + (size_t)h * 64 * DMODEL + d0;
#pragma unroll
        for (int j = 0; j < 16; j++) {
            int u = t + j * 256;
            int e = u >> 6, dc = u & 63;
            out[(size_t)e * DMODEL + dc] = __float2half_rn(tile[dc * 65 + e]);
        }
    } else {
        int d0 = blockIdx.x * 64, c0 = blockIdx.y * 64;
#pragma unroll
        for (int j = 0; j < 16; j++) {
            int u = t + j * 256;
            tile[(u >> 6) * 65 + (u & 63)] = WO[(size_t)(d0 + (u >> 6)) * DMODEL + c0 + (u & 63)];
        }
        __syncthreads();
#pragma unroll
        for (int j = 0; j < 16; j++) {
            int u = t + j * 256;
            int cr = u >> 6, dc = u & 63;
            g_WOth[(size_t)(c0 + cr) * DMODEL + d0 + dc] = __float2half_rn(tile[dc * 65 + cr]);
        }
    }
}

// ---------------------------------------------------------------------------
// proj_kernel: all three projections, fp16, BM=64 x BN=128 tiles, 2x4 warps ->
// warp 32x32, BK=64, 3-stage, single-sync, occupancy 3. z -> g_Qh/g_Kh/g_Vh.
// ---------------------------------------------------------------------------
__global__ __launch_bounds__(256, 3) void proj_kernel() {
    extern __shared__ float smf[];
    uint32_t sA = smem_u32(smf);           // [3][64 x 128B]  = 24KB
    uint32_t sB = sA + 3 * 8192;           // [3][128 x 128B] = 48KB

    int t = threadIdx.x, wid = t >> 5;
    int wm = wid & 1, wn = wid >> 1;       // 2x4 warps -> 64x128, warp 32x32
    int m0 = blockIdx.x * 64, n0 = blockIdx.y * 128, which = blockIdx.z;
    LANE_OFFS();

    const __half* A = g_Xh + (size_t)which * MROWS * DMODEL + (size_t)m0 * DMODEL;
    const __half* B = g_Wth + (size_t)which * DMODEL * DMODEL + (size_t)n0 * DMODEL;

    uint32_t aOffU = (uint32_t)(wm * 32 + aRow) * 128 + aK16;
    uint32_t bOffU = (uint32_t)(wn * 32 + bRow) * 128 + bK16;

    float acc[2][4][4];
#pragma unroll
    for (int mi = 0; mi < 2; mi++)
#pragma unroll
        for (int nj = 0; nj < 4; nj++)
#pragma unroll
            for (int e = 0; e < 4; e++) acc[mi][nj][e] = 0.0f;

    auto issue = [&](int it3) {
        int s = it3 % 3;
        int kk = it3 * 64;
        uint32_t bA = sA + s * 8192;
        uint32_t bB = sB + s * 16384;
#pragma unroll
        for (int j = 0; j < 2; j++) {          // A: 64 rows x 128B
            int u = t + j * 256;
            int row = u >> 3, ch = u & 7;
            cp16a(bA + swz(row * 128 + ch * 16), A + (size_t)row * DMODEL + kk + ch * 8);
        }
#pragma unroll
        for (int j = 0; j < 4; j++) {          // B: 128 rows x 128B
            int u = t + j * 256;
            int row = u >> 3, ch = u & 7;
            cp16a(bB + swz(row * 128 + ch * 16), B + (size_t)row * DMODEL + kk + ch * 8);
        }
    };

    issue(0); cp_commit();
    issue(1); cp_commit();
#pragma unroll 1
    for (int it = 0; it < 16; it++) {
        if (it < 15) cp_wait<1>(); else cp_wait<0>();
        __syncthreads();
        uint32_t bA = sA + (it % 3) * 8192;
        uint32_t bB = sB + (it % 3) * 16384;
#pragma unroll
        for (int slab = 0; slab < 4; slab++) {
            uint32_t a[2][4], b[2][4];
            ldsm4(a[0], bA + swz(aOffU + slab * 32));
            ldsm4(a[1], bA + swz(aOffU + 2048 + slab * 32));
            ldsm4(b[0], bB + swz(bOffU + slab * 32));
            ldsm4(b[1], bB + swz(bOffU + 2048 + slab * 32));
#pragma unroll
            for (int mi = 0; mi < 2; mi++)
#pragma unroll
                for (int nj = 0; nj < 4; nj++)
                    mma16h(acc[mi][nj], a[mi], &b[nj >> 1][(nj & 1) * 2]);
        }
        if (it + 2 < 16) { issue(it + 2); cp_commit(); }
    }

    __half* Outp = (which == 0) ? g_Qh : (which == 1) ? g_Kh : g_Vh;
#pragma unroll
    for (int mi = 0; mi < 2; mi++) {
        int mrow = m0 + wm * 32 + mi * 16 + gg;
#pragma unroll
        for (int nj = 0; nj < 4; nj++) {
            int col = n0 + wn * 32 + nj * 8 + 2 * tt;
            int b = mrow >> 11, s = mrow & (SEQ - 1);
            int h = col >> 6, e = col & 63;
            __half* dst = Outp + ((size_t)(b * NHEAD + h) * SEQ + s) * DHEAD + e;
            *(__half2*)dst = __floats2half2_rn(acc[mi][nj][0], acc[mi][nj][1]);
            *(__half2*)(dst + 8 * DHEAD) = __floats2half2_rn(acc[mi][nj][2], acc[mi][nj][3]);
        }
    }
}

// ---------------------------------------------------------------------------
// out_kernel (fp16, 128x128, BK=64, 3-stage, single-sync): Out = Ocat @ WOt^T.
// ---------------------------------------------------------------------------
__global__ __launch_bounds__(256, 2) void out_kernel(float* __restrict__ Cout) {
    extern __shared__ float smf[];
    uint32_t sA = smem_u32(smf);
    uint32_t sB = sA + 3 * 16384;

    int t = threadIdx.x, wid = t >> 5;
    int wm = wid & 1, wn = wid >> 1;
    int m0 = blockIdx.x * 128, n0 = blockIdx.y * 128;
    LANE_OFFS();

    const __half* A = g_Ocat + (size_t)m0 * DMODEL;
    const __half* B = g_WOth + (size_t)n0 * DMODEL;

    float acc[4][4][4];
#pragma unroll
    for (int mi = 0; mi < 4; mi++)
#pragma unroll
        for (int nj = 0; nj < 4; nj++)
#pragma unroll
            for (int e = 0; e < 4; e++) acc[mi][nj][e] = 0.0f;

    auto issue = [&](int it3) {
        int s = it3 % 3;
        int kk = it3 * 64;
        uint32_t bA = sA + s * 16384;
        uint32_t bB = sB + s * 16384;
#pragma unroll
        for (int j = 0; j < 4; j++) {
            int u = t + j * 256;
            int row = u >> 3, ch = u & 7;
            uint32_t off = swz(row * 128 + ch * 16);
            cp16a(bA + off, A + (size_t)row * DMODEL + kk + ch * 8);
            cp16a(bB + off, B + (size_t)row * DMODEL + kk + ch * 8);
        }
    };

    uint32_t aOffU = (uint32_t)(wm * 64 + aRow) * 128 + aK16;
    uint32_t bOffU = (uint32_t)(wn * 32 + bRow) * 128 + bK16;

    issue(0); cp_commit();
    issue(1); cp_commit();
#pragma unroll 1
    for (int it = 0; it < 16; it++) {
        if (it < 15) cp_wait<1>(); else cp_wait<0>();
        __syncthreads();
        uint32_t bA = sA + (it % 3) * 16384;
        uint32_t bB = sB + (it % 3) * 16384;
#pragma unroll
        for (int slab = 0; slab < 4; slab++) {
            uint32_t a[4][4], b[2][4];
#pragma unroll
            for (int mi = 0; mi < 4; mi++)
                ldsm4(a[mi], bA + swz(aOffU + mi * 2048 + slab * 32));
#pragma unroll
            for (int g2 = 0; g2 < 2; g2++)
                ldsm4(b[g2], bB + swz(bOffU + g2 * 2048 + slab * 32));
#pragma unroll
            for (int mi = 0; mi < 4; mi++)
#pragma unroll
                for (int nj = 0; nj < 4; nj++)
                    mma16h(acc[mi][nj], a[mi], &b[nj >> 1][(nj & 1) * 2]);
        }
        if (it + 2 < 16) { issue(it + 2); cp_commit(); }
    }

#pragma unroll
    for (int mi = 0; mi < 4; mi++) {
        int mrow = m0 + wm * 64 + mi * 16 + gg;
#pragma unroll
        for (int nj = 0; nj < 4; nj++) {
            int col = n0 + wn * 32 + nj * 8 + 2 * tt;
            float* d0 = Cout + (size_t)mrow * DMODEL + col;
            *(float2*)d0 = make_float2(acc[mi][nj][0], acc[mi][nj][1]);
            *(float2*)(d0 + 8 * DMODEL) = make_float2(acc[mi][nj][2], acc[mi][nj][3]);
        }
    }
}

// ---------------------------------------------------------------------------
// den_kernel (R12 structure: 128q x 64k stripes, 1024 balanced blocks):
//   S = Q K^T (Q double-buffered 16KB tiles), P -> g_Ph fp16 (LOCAL column
//   index); colsums in registers; fp16 V stripe scaled + transposed -> g_Vt.
// ---------------------------------------------------------------------------
__global__ __launch_bounds__(256, 2) void den_kernel() {
    int kt = blockIdx.x;          // kt=0 heaviest first
    int bh = blockIdx.y;

    extern __shared__ float smf[];
    uint32_t sK = smem_u32(smf);                 // fp16 K stripe: 8KB
    uint32_t sQ = sK + 8192;                     // fp16 Q tiles: 2 x 16KB
    float* Vstage = (float*)((char*)smf + 8192 + 32768);  // [64][65] fp32
    __shared__ float colsum[4][64];
    __shared__ float invs[64];

    int t = threadIdx.x, wid = t >> 5;
    int wm = wid & 3, wn = wid >> 2;             // 4x2 warps -> 128q x 64k
    LANE_OFFS();

    const __half* Qg = g_Qh + (size_t)bh * SEQ * DHEAD;
    const __half* Kg = g_Kh + ((size_t)bh * SEQ + kt * 64) * DHEAD;
    __half* Pb = g_Ph + (size_t)bh * SEQ * SEQ + kt * 64;

    auto issueQ = [&](int qt, int s) {
        const __half* src = Qg + (size_t)qt * 128 * DHEAD;
        uint32_t base = sQ + s * 16384;
#pragma unroll
        for (int j = 0; j < 4; j++) {
            int u = t + j * 256;
            int row = u >> 3, ch = u & 7;
            cp16a(base + swz(row * 128 + ch * 16), src + (size_t)row * DHEAD + ch * 8);
        }
    };

#pragma unroll
    for (int j = 0; j < 2; j++) {
        int u = t + j * 256;
        int row = u >> 3, ch = u & 7;
        cp16a(sK + swz(row * 128 + ch * 16), Kg + (size_t)row * DHEAD + ch * 8);
    }
    int qt0 = kt >> 1;
    issueQ(qt0, 0); cp_commit(); cp_wait<0>(); __syncthreads();

    uint32_t aOffU = (uint32_t)(wm * 32 + aRow) * 128 + aK16;
    uint32_t bOffU = (uint32_t)(wn * 32 + bRow) * 128 + bK16;

    float part[4][2];
#pragma unroll
    for (int nj = 0; nj < 4; nj++) { part[nj][0] = 0.0f; part[nj][1] = 0.0f; }

#pragma unroll 1
    for (int qt = qt0; qt < SEQ / 128; qt++) {
        int it = qt - qt0;
        if (qt + 1 < SEQ / 128) { issueQ(qt + 1, (it + 1) & 1); cp_commit(); }

        uint32_t baQ = sQ + (it & 1) * 16384;
        float acc[2][4][4];
#pragma unroll
        for (int mi = 0; mi < 2; mi++)
#pragma unroll
            for (int nj = 0; nj < 4; nj++)
#pragma unroll
                for (int e = 0; e < 4; e++) acc[mi][nj][e] = 0.0f;

#pragma unroll
        for (int slab = 0; slab < 4; slab++) {
            uint32_t a[2][4], b[2][4];
            ldsm4(a[0], baQ + swz(aOffU + slab * 32));
            ldsm4(a[1], baQ + swz(aOffU + 2048 + slab * 32));
            ldsm4(b[0], sK + swz(bOffU + slab * 32));
            ldsm4(b[1], sK + swz(bOffU + 2048 + slab * 32));
#pragma unroll
            for (int mi = 0; mi < 2; mi++)
#pragma unroll
                for (int nj = 0; nj < 4; nj++)
                    mma16h(acc[mi][nj], a[mi], &b[nj >> 1][(nj & 1) * 2]);
        }

        int q0 = qt * 128;
#pragma unroll
        for (int mi = 0; mi < 2; mi++) {
            int row = wm * 32 + mi * 16 + gg;
            int q = q0 + row;
#pragma unroll
            for (int nj = 0; nj < 4; nj++) {
                int kl = wn * 32 + nj * 8 + 2 * tt;   // local column within stripe
                int kg = kt * 64 + kl;                // global k (mask/bias only)
                float v0 = (kg     <= q) ? __expf((acc[mi][nj][0] + (float)(kg - q)) * SCALE) : 0.0f;
                float v1 = (kg + 1 <= q) ? __expf((acc[mi][nj][1] + (float)(kg + 1 - q)) * SCALE) : 0.0f;
                float v2 = (kg     <= q + 8) ? __expf((acc[mi][nj][2] + (float)(kg - q - 8)) * SCALE) : 0.0f;
                float v3 = (kg + 1 <= q + 8) ? __expf((acc[mi][nj][3] + (float)(kg + 1 - q - 8)) * SCALE) : 0.0f;
                part[nj][0] += v0 + v2;
                part[nj][1] += v1 + v3;
                *(__half2*)&Pb[(size_t)q * SEQ + kl] = __floats2half2_rn(v0, v1);
                *(__half2*)&Pb[(size_t)(q + 8) * SEQ + kl] = __floats2half2_rn(v2, v3);
            }
        }
        cp_wait<0>(); __syncthreads();
    }

#pragma unroll
    for (int nj = 0; nj < 4; nj++)
#pragma unroll
        for (int p = 0; p < 2; p++) {
            float v = part[nj][p];
            v += __shfl_xor_sync(0xffffffffu, v, 4);
            v += __shfl_xor_sync(0xffffffffu, v, 8);
            v += __shfl_xor_sync(0xffffffffu, v, 16);
            part[nj][p] = v;
        }
    if (lane < 4) {
#pragma unroll
        for (int nj = 0; nj < 4; nj++) {
            colsum[wm][wn * 32 + nj * 8 + 2 * lane]     = part[nj][0];
            colsum[wm][wn * 32 + nj * 8 + 2 * lane + 1] = part[nj][1];
        }
    }
    __syncthreads();
    if (t < 64)
        invs[t] = 1.0f / (colsum[0][t] + colsum[1][t] + colsum[2][t] + colsum[3][t]);
    __syncthreads();

    // scale + transpose fp16 V stripe -> g_Vt (staging pitch 65)
    const __half* Vg = g_Vh + ((size_t)bh * SEQ + kt * 64) * DHEAD;
#pragma unroll
    for (int j = 0; j < 2; j++) {
        int u = t + j * 256;                 // 512 x 16B covers 64x64 halves
        int r = u >> 3, e8 = (u & 7) * 8;
        uint4 raw = *(const uint4*)&Vg[(size_t)r * DHEAD + e8];
        float iv = invs[r];
        __half2 h0 = *(__half2*)&raw.x, h1 = *(__half2*)&raw.y;
        __half2 h2 = *(__half2*)&raw.z, h3 = *(__half2*)&raw.w;
        Vstage[r * 65 + e8 + 0] = __low2float(h0) * iv;
        Vstage[r * 65 + e8 + 1] = __high2float(h0) * iv;
        Vstage[r * 65 + e8 + 2] = __low2float(h1) * iv;
        Vstage[r * 65 + e8 + 3] = __high2float(h1) * iv;
        Vstage[r * 65 + e8 + 4] = __low2float(h2) * iv;
        Vstage[r * 65 + e8 + 5] = __high2float(h2) * iv;
        Vstage[r * 65 + e8 + 6] = __low2float(h3) * iv;
        Vstage[r * 65 + e8 + 7] = __high2float(h3) * iv;
    }
    __syncthreads();
    __half* Vt = g_Vt + (size_t)bh * DHEAD * SEQ + kt * 64;
#pragma unroll
    for (int er = 0; er < 8; er++) {
        int e = wid * 8 + er;
#pragma unroll
        for (int half_ = 0; half_ < 2; half_++) {
            int r = lane + half_ * 32;
            Vt[(size_t)e * SEQ + r] = __float2half_rn(Vstage[r * 65 + e]);
        }
    }
}

// ---------------------------------------------------------------------------
// pv_kernel (fp16): Ocat[128q x 64e] = P @ Vt^T, BK=64, 3-stage, occupancy 3.
// ---------------------------------------------------------------------------
__global__ __launch_bounds__(256, 3) void pv_kernel() {
    int qt = (int)gridDim.x - 1 - blockIdx.x;
    int bh = blockIdx.y;
    int b = bh >> 4, h = bh & 15;

    extern __shared__ float smf[];
    uint32_t sP = smem_u32(smf);                 // [3][128 x 128B] = 48KB
    uint32_t sV = sP + 3 * 16384;                // [3][64 x 128B]  = 24KB

    int t = threadIdx.x, wid = t >> 5;
    int wm = wid & 3, wn = wid >> 2;
    LANE_OFFS();

    const __half* Pg = g_Ph + ((size_t)bh * SEQ + qt * 128) * SEQ;
    const __half* Vtg = g_Vt + (size_t)bh * DHEAD * SEQ;

    float acc[2][4][4];
#pragma unroll
    for (int mi = 0; mi < 2; mi++)
#pragma unroll
        for (int nj = 0; nj < 4; nj++)
#pragma unroll
            for (int e = 0; e < 4; e++) acc[mi][nj][e] = 0.0f;

    int niter = 2 * qt + 2;

    auto issue = [&](int it3) {
        int s = it3 % 3;
        uint32_t bP = sP + s * 16384;
#pragma unroll
        for (int j = 0; j < 4; j++) {
            int u = t + j * 256;
            int row = u >> 3, ch = u & 7;
            cp16a(bP + swz(row * 128 + ch * 16), Pg + (size_t)row * SEQ + it3 * 64 + ch * 8);
        }
        uint32_t bV = sV + s * 8192;
#pragma unroll
        for (int j = 0; j < 2; j++) {
            int u = t + j * 256;
            int row = u >> 3, ch = u & 7;
            cp16a(bV + swz(row * 128 + ch * 16), Vtg + (size_t)row * SEQ + it3 * 64 + ch * 8);
        }
    };

    uint32_t aOffU = (uint32_t)(wm * 32 + aRow) * 128 + aK16;
    uint32_t bOffU = (uint32_t)(wn * 32 + bRow) * 128 + bK16;

    issue(0); cp_commit();
    if (niter > 1) { issue(1); cp_commit(); }
#pragma unroll 1
    for (int it = 0; it < niter; it++) {
        if (it + 1 < niter) cp_wait<1>(); else cp_wait<0>();
        __syncthreads();
        uint32_t bP = sP + (it % 3) * 16384;
        uint32_t bV = sV + (it % 3) * 8192;
#pragma unroll
        for (int slab = 0; slab < 4; slab++) {
            uint32_t a[2][4], bfr[2][4];
            ldsm4(a[0], bP + swz(aOffU + slab * 32));
            ldsm4(a[1], bP + swz(aOffU + 2048 + slab * 32));
            ldsm4(bfr[0], bV + swz(bOffU + slab * 32));
            ldsm4(bfr[1], bV + swz(bOffU + 2048 + slab * 32));
#pragma unroll
            for (int mi = 0; mi < 2; mi++)
#pragma unroll
                for (int nj = 0; nj < 4; nj++)
                    mma16h(acc[mi][nj], a[mi], &bfr[nj >> 1][(nj & 1) * 2]);
        }
        if (it + 2 < niter) { issue(it + 2); cp_commit(); }
    }

#pragma unroll
    for (int mi = 0; mi < 2; mi++) {
        int row = qt * 128 + wm * 32 + mi * 16 + gg;
#pragma unroll
        for (int nj = 0; nj < 4; nj++) {
            int colL = wn * 32 + nj * 8 + 2 * tt;
            __half* d0 = g_Ocat + ((size_t)(b * SEQ) + row) * DMODEL + h * 64 + colL;
            *(__half2*)d0 = __floats2half2_rn(acc[mi][nj][0], acc[mi][nj][1]);
            *(__half2*)(d0 + 8 * DMODEL) = __floats2half2_rn(acc[mi][nj][2], acc[mi][nj][3]);
        }
    }
}

// ---------------------------------------------------------------------------
// Launch. Inputs: keys, queries, values, WQ, WK, WV, WO, masking
// ---------------------------------------------------------------------------
extern "C" void kernel_launch(void* const* d_in, const int* in_sizes, int n_in,
                              void* d_out, int out_size) {
    const float* keys    = (const float*)d_in[0];
    const float* queries = (const float*)d_in[1];
    const float* values  = (const float*)d_in[2];
    const float* WQ      = (const float*)d_in[3];
    const float* WK      = (const float*)d_in[4];
    const float* WV      = (const float*)d_in[5];
    const float* WO      = (const float*)d_in[6];
    float* out = (float*)d_out;
    (void)in_sizes; (void)n_in; (void)out_size;

    const int projSmem = 3 * 8192 + 3 * 16384;                // 73728
    const int outSmem  = 3 * 16384 * 2;                       // 98304
    const int denSmem  = 8192 + 2 * 16384 + 64 * 65 * 4;      // 57600
    const int pvSmem   = 3 * 16384 + 3 * 8192;                // 73728
    cudaFuncSetAttribute(proj_kernel, cudaFuncAttributeMaxDynamicSharedMemorySize, projSmem);
    cudaFuncSetAttribute(out_kernel,  cudaFuncAttributeMaxDynamicSharedMemorySize, outSmem);
    cudaFuncSetAttribute(den_kernel,  cudaFuncAttributeMaxDynamicSharedMemorySize, denSmem);
    cudaFuncSetAttribute(pv_kernel,   cudaFuncAttributeMaxDynamicSharedMemorySize, pvSmem);

    // prologue (all fp16)
    xprep_kernel<<<dim3(MROWS * DMODEL / 4 / 256, 1, 3), 256>>>(
        (const float4*)queries, (const float4*)keys, (const float4*)values);
    wprep_kernel<<<dim3(DMODEL / 64, 16, 4), 256>>>(WQ, WK, WV, WO);

    // projections, fine-grain tiles (z=0 Q, z=1 K, z=2 V)
    proj_kernel<<<dim3(MROWS / 64, DMODEL / 128, 3), 256, projSmem>>>();

    // attention (fp16): den uses R12 stripe tiling (balanced 1024 blocks)
    den_kernel<<<dim3(SEQ / 64, BH), 256, denSmem>>>();
    pv_kernel<<<dim3(SEQ / 128, BH), 256, pvSmem>>>();

    // output projection (fp16)
    out_kernel<<<dim3(MROWS / 128, DMODEL / 128), 256, outSmem>>>(out);
}

// round 15
// speedup vs baseline: 1.1602x; 1.0888x over previous
#include <cuda_runtime.h>
#include <cuda_fp16.h>
#include <cstdint>
#include <cstddef>

#define BATCH  2
#define SEQ    2048
#define DMODEL 1024
#define NHEAD  16
#define DHEAD  64
#define BH     (BATCH*NHEAD)
#define MROWS  (BATCH*SEQ)
#define SCALE  0.022097086912079608f   // 1/sqrt(2048)
#define S2LOG  0.031883924137085614f   // SCALE * log2(e)

// ---------------- scratch (device globals; allocation-free rule) -----------
__device__ __align__(16) __half g_Xh[(size_t)3 * MROWS * DMODEL];    // fp16 q/k/v inputs
__device__ __align__(16) __half g_Wth[(size_t)3 * DMODEL * DMODEL];  // fp16 n-major WQ/WK/WV
__device__ __align__(16) __half g_WOth[(size_t)DMODEL * DMODEL];     // fp16 n-major WO
__device__ __align__(16) __half g_Qh[(size_t)BH * SEQ * DHEAD];
__device__ __align__(16) __half g_Kh[(size_t)BH * SEQ * DHEAD];
__device__ __align__(16) __half g_Vh[(size_t)BH * SEQ * DHEAD];
__device__ __align__(16) __half g_Vt[(size_t)BH * DHEAD * SEQ];      // [bh][e][k], scaled 1/den
__device__ __align__(16) __half g_Ph[(size_t)BH * SEQ * SEQ];        // exp(scores) fp16
__device__ __align__(16) __half g_Ocat[(size_t)MROWS * DMODEL];      // fp16 attention output

// ---------------- helpers ---------------------------------------------------
__device__ __forceinline__ uint32_t swz(uint32_t o) { return o ^ ((o >> 3) & 0x70); }
__device__ __forceinline__ uint32_t smem_u32(const void* p) {
    return (uint32_t)__cvta_generic_to_shared(p);
}
__device__ __forceinline__ void cp16a(uint32_t saddr, const void* gmem) {
    asm volatile("cp.async.cg.shared.global [%0], [%1], 16;" :: "r"(saddr), "l"(gmem));
}
__device__ __forceinline__ void cp_commit() { asm volatile("cp.async.commit_group;"); }
template <int N> __device__ __forceinline__ void cp_wait() {
    asm volatile("cp.async.wait_group %0;" :: "n"(N));
}
__device__ __forceinline__ void ldsm4(uint32_t (&r)[4], uint32_t saddr) {
    asm volatile("ldmatrix.sync.aligned.m8n8.x4.shared.b16 {%0,%1,%2,%3}, [%4];"
                 : "=r"(r[0]), "=r"(r[1]), "=r"(r[2]), "=r"(r[3]) : "r"(saddr));
}
__device__ __forceinline__ void mma16h(float (&c)[4], const uint32_t (&a)[4], const uint32_t* b) {
    asm volatile(
        "mma.sync.aligned.m16n8k16.row.col.f32.f16.f16.f32 "
        "{%0,%1,%2,%3}, {%4,%5,%6,%7}, {%8,%9}, {%0,%1,%2,%3};"
        : "+f"(c[0]), "+f"(c[1]), "+f"(c[2]), "+f"(c[3])
        : "r"(a[0]), "r"(a[1]), "r"(a[2]), "r"(a[3]), "r"(b[0]), "r"(b[1]));
}
__device__ __forceinline__ float ex2f(float x) {
    float r;
    asm("ex2.approx.f32 %0, %1;" : "=f"(r) : "f"(x));
    return r;
}
#define LANE_OFFS() \
    int lane = threadIdx.x & 31; \
    int aRow = ((lane >> 3) & 1) * 8 + (lane & 7); \
    int aK16 = (lane >> 4) * 16; \
    int bRow = (lane >> 4) * 8 + (lane & 7); \
    int bK16 = ((lane >> 3) & 1) * 16; \
    int gg = lane >> 2, tt = lane & 3; (void)gg; (void)tt;

// ---------------------------------------------------------------------------
// Prologue: queries/keys/values -> fp16
// ---------------------------------------------------------------------------
__global__ __launch_bounds__(256) void xprep_kernel(const float4* __restrict__ q,
                                                    const float4* __restrict__ k,
                                                    const float4* __restrict__ v) {
    int which = blockIdx.z;
    const float4* src = (which == 0) ? q : (which == 1) ? k : v;
    size_t i = (size_t)blockIdx.x * 256 + threadIdx.x;
    float4 x = src[i];
    __half* dst = g_Xh + (size_t)which * MROWS * DMODEL + i * 4;
    *(__half2*)dst = __floats2half2_rn(x.x, x.y);
    *(__half2*)(dst + 2) = __floats2half2_rn(x.z, x.w);
}

// z<3: W[h][d][e] -> fp16 n-major [h*64+e][d]; z==3: WO[d][c] -> fp16 [c][d]
__global__ __launch_bounds__(256) void wprep_kernel(const float* __restrict__ WQ,
                                                    const float* __restrict__ WK,
                                                    const float* __restrict__ WV,
                                                    const float* __restrict__ WO) {
    int which = blockIdx.z;
    __shared__ float tile[64 * 65];
    int t = threadIdx.x;
    if (which < 3) {
        int h = blockIdx.y, d0 = blockIdx.x * 64;
        const float* W = ((which == 0) ? WQ : (which == 1) ? WK : WV)
                         + ((size_t)h * DMODEL + d0) * DHEAD;
#pragma unroll
        for (int j = 0; j < 16; j++) {
            int u = t + j * 256;
            tile[(u >> 6) * 65 + (u & 63)] = W[(size_t)(u >> 6) * DHEAD + (u & 63)];
        }
        __syncthreads();
        __half* out = g_Wth + (size_t)which * DMODEL * DMODEL + (size_t)h * 64 * DMODEL + d0;
#pragma unroll
        for (int j = 0; j < 16; j++) {
            int u = t + j * 256;
            int e = u >> 6, dc = u & 63;
            out[(size_t)e * DMODEL + dc] = __float2half_rn(tile[dc * 65 + e]);
        }
    } else {
        int d0 = blockIdx.x * 64, c0 = blockIdx.y * 64;
#pragma unroll
        for (int j = 0; j < 16; j++) {
            int u = t + j * 256;
            tile[(u >> 6) * 65 + (u & 63)] = WO[(size_t)(d0 + (u >> 6)) * DMODEL + c0 + (u & 63)];
        }
        __syncthreads();
#pragma unroll
        for (int j = 0; j < 16; j++) {
            int u = t + j * 256;
            int cr = u >> 6, dc = u & 63;
            g_WOth[(size_t)(c0 + cr) * DMODEL + d0 + dc] = __float2half_rn(tile[dc * 65 + cr]);
        }
    }
}

// ---------------------------------------------------------------------------
// proj_kernel: all three projections, fp16, BM=64 x BN=128 tiles, 2x4 warps ->
// warp 32x32, BK=64, 3-stage, single-sync, occupancy 3. z -> g_Qh/g_Kh/g_Vh.
// ---------------------------------------------------------------------------
__global__ __launch_bounds__(256, 3) void proj_kernel() {
    extern __shared__ float smf[];
    uint32_t sA = smem_u32(smf);           // [3][64 x 128B]  = 24KB
    uint32_t sB = sA + 3 * 8192;           // [3][128 x 128B] = 48KB

    int t = threadIdx.x, wid = t >> 5;
    int wm = wid & 1, wn = wid >> 1;       // 2x4 warps -> 64x128, warp 32x32
    int m0 = blockIdx.x * 64, n0 = blockIdx.y * 128, which = blockIdx.z;
    LANE_OFFS();

    const __half* A = g_Xh + (size_t)which * MROWS * DMODEL + (size_t)m0 * DMODEL;
    const __half* B = g_Wth + (size_t)which * DMODEL * DMODEL + (size_t)n0 * DMODEL;

    uint32_t aOffU = (uint32_t)(wm * 32 + aRow) * 128 + aK16;
    uint32_t bOffU = (uint32_t)(wn * 32 + bRow) * 128 + bK16;

    float acc[2][4][4];
#pragma unroll
    for (int mi = 0; mi < 2; mi++)
#pragma unroll
        for (int nj = 0; nj < 4; nj++)
#pragma unroll
            for (int e = 0; e < 4; e++) acc[mi][nj][e] = 0.0f;

    auto issue = [&](int it3) {
        int s = it3 % 3;
        int kk = it3 * 64;
        uint32_t bA = sA + s * 8192;
        uint32_t bB = sB + s * 16384;
#pragma unroll
        for (int j = 0; j < 2; j++) {          // A: 64 rows x 128B
            int u = t + j * 256;
            int row = u >> 3, ch = u & 7;
            cp16a(bA + swz(row * 128 + ch * 16), A + (size_t)row * DMODEL + kk + ch * 8);
        }
#pragma unroll
        for (int j = 0; j < 4; j++) {          // B: 128 rows x 128B
            int u = t + j * 256;
            int row = u >> 3, ch = u & 7;
            cp16a(bB + swz(row * 128 + ch * 16), B + (size_t)row * DMODEL + kk + ch * 8);
        }
    };

    issue(0); cp_commit();
    issue(1); cp_commit();
#pragma unroll 1
    for (int it = 0; it < 16; it++) {
        if (it < 15) cp_wait<1>(); else cp_wait<0>();
        __syncthreads();
        uint32_t bA = sA + (it % 3) * 8192;
        uint32_t bB = sB + (it % 3) * 16384;
#pragma unroll
        for (int slab = 0; slab < 4; slab++) {
            uint32_t a[2][4], b[2][4];
            ldsm4(a[0], bA + swz(aOffU + slab * 32));
            ldsm4(a[1], bA + swz(aOffU + 2048 + slab * 32));
            ldsm4(b[0], bB + swz(bOffU + slab * 32));
            ldsm4(b[1], bB + swz(bOffU + 2048 + slab * 32));
#pragma unroll
            for (int mi = 0; mi < 2; mi++)
#pragma unroll
                for (int nj = 0; nj < 4; nj++)
                    mma16h(acc[mi][nj], a[mi], &b[nj >> 1][(nj & 1) * 2]);
        }
        if (it + 2 < 16) { issue(it + 2); cp_commit(); }
    }

    __half* Outp = (which == 0) ? g_Qh : (which == 1) ? g_Kh : g_Vh;
#pragma unroll
    for (int mi = 0; mi < 2; mi++) {
        int mrow = m0 + wm * 32 + mi * 16 + gg;
#pragma unroll
        for (int nj = 0; nj < 4; nj++) {
            int col = n0 + wn * 32 + nj * 8 + 2 * tt;
            int b = mrow >> 11, s = mrow & (SEQ - 1);
            int h = col >> 6, e = col & 63;
            __half* dst = Outp + ((size_t)(b * NHEAD + h) * SEQ + s) * DHEAD + e;
            *(__half2*)dst = __floats2half2_rn(acc[mi][nj][0], acc[mi][nj][1]);
            *(__half2*)(dst + 8 * DHEAD) = __floats2half2_rn(acc[mi][nj][2], acc[mi][nj][3]);
        }
    }
}

// ---------------------------------------------------------------------------
// out_kernel (fp16, 128x128, BK=64, 3-stage, single-sync): Out = Ocat @ WOt^T.
// ---------------------------------------------------------------------------
__global__ __launch_bounds__(256, 2) void out_kernel(float* __restrict__ Cout) {
    extern __shared__ float smf[];
    uint32_t sA = smem_u32(smf);
    uint32_t sB = sA + 3 * 16384;

    int t = threadIdx.x, wid = t >> 5;
    int wm = wid & 1, wn = wid >> 1;
    int m0 = blockIdx.x * 128, n0 = blockIdx.y * 128;
    LANE_OFFS();

    const __half* A = g_Ocat + (size_t)m0 * DMODEL;
    const __half* B = g_WOth + (size_t)n0 * DMODEL;

    float acc[4][4][4];
#pragma unroll
    for (int mi = 0; mi < 4; mi++)
#pragma unroll
        for (int nj = 0; nj < 4; nj++)
#pragma unroll
            for (int e = 0; e < 4; e++) acc[mi][nj][e] = 0.0f;

    auto issue = [&](int it3) {
        int s = it3 % 3;
        int kk = it3 * 64;
        uint32_t bA = sA + s * 16384;
        uint32_t bB = sB + s * 16384;
#pragma unroll
        for (int j = 0; j < 4; j++) {
            int u = t + j * 256;
            int row = u >> 3, ch = u & 7;
            uint32_t off = swz(row * 128 + ch * 16);
            cp16a(bA + off, A + (size_t)row * DMODEL + kk + ch * 8);
            cp16a(bB + off, B + (size_t)row * DMODEL + kk + ch * 8);
        }
    };

    uint32_t aOffU = (uint32_t)(wm * 64 + aRow) * 128 + aK16;
    uint32_t bOffU = (uint32_t)(wn * 32 + bRow) * 128 + bK16;

    issue(0); cp_commit();
    issue(1); cp_commit();
#pragma unroll 1
    for (int it = 0; it < 16; it++) {
        if (it < 15) cp_wait<1>(); else cp_wait<0>();
        __syncthreads();
        uint32_t bA = sA + (it % 3) * 16384;
        uint32_t bB = sB + (it % 3) * 16384;
#pragma unroll
        for (int slab = 0; slab < 4; slab++) {
            uint32_t a[4][4], b[2][4];
#pragma unroll
            for (int mi = 0; mi < 4; mi++)
                ldsm4(a[mi], bA + swz(aOffU + mi * 2048 + slab * 32));
#pragma unroll
            for (int g2 = 0; g2 < 2; g2++)
                ldsm4(b[g2], bB + swz(bOffU + g2 * 2048 + slab * 32));
#pragma unroll
            for (int mi = 0; mi < 4; mi++)
#pragma unroll
                for (int nj = 0; nj < 4; nj++)
                    mma16h(acc[mi][nj], a[mi], &b[nj >> 1][(nj & 1) * 2]);
        }
        if (it + 2 < 16) { issue(it + 2); cp_commit(); }
    }

#pragma unroll
    for (int mi = 0; mi < 4; mi++) {
        int mrow = m0 + wm * 64 + mi * 16 + gg;
#pragma unroll
        for (int nj = 0; nj < 4; nj++) {
            int col = n0 + wn * 32 + nj * 8 + 2 * tt;
            float* d0 = Cout + (size_t)mrow * DMODEL + col;
            *(float2*)d0 = make_float2(acc[mi][nj][0], acc[mi][nj][1]);
            *(float2*)(d0 + 8 * DMODEL) = make_float2(acc[mi][nj][2], acc[mi][nj][3]);
        }
    }
}

// ---------------------------------------------------------------------------
// den_kernel (128q x 64k stripes): S = Q K^T; P = exp -> g_Ph fp16 via
// log2-domain epilogue with ex2.approx; masking only on iteration 0 (exact
// integer compares there); colsums in registers; V scaled+transposed -> g_Vt.
// ---------------------------------------------------------------------------
__global__ __launch_bounds__(256, 2) void den_kernel() {
    int kt = blockIdx.x;          // kt=0 heaviest first
    int bh = blockIdx.y;

    extern __shared__ float smf[];
    uint32_t sK = smem_u32(smf);                 // fp16 K stripe: 8KB
    uint32_t sQ = sK + 8192;                     // fp16 Q tiles: 2 x 16KB
    float* Vstage = (float*)((char*)smf + 8192 + 32768);  // [64][65] fp32
    __shared__ float colsum[4][64];
    __shared__ float invs[64];

    int t = threadIdx.x, wid = t >> 5;
    int wm = wid & 3, wn = wid >> 2;             // 4x2 warps -> 128q x 64k
    LANE_OFFS();

    const __half* Qg = g_Qh + (size_t)bh * SEQ * DHEAD;
    const __half* Kg = g_Kh + ((size_t)bh * SEQ + kt * 64) * DHEAD;
    __half* Pb = g_Ph + (size_t)bh * SEQ * SEQ + kt * 64;

    auto issueQ = [&](int qt, int s) {
        const __half* src = Qg + (size_t)qt * 128 * DHEAD;
        uint32_t base = sQ + s * 16384;
#pragma unroll
        for (int j = 0; j < 4; j++) {
            int u = t + j * 256;
            int row = u >> 3, ch = u & 7;
            cp16a(base + swz(row * 128 + ch * 16), src + (size_t)row * DHEAD + ch * 8);
        }
    };

#pragma unroll
    for (int j = 0; j < 2; j++) {
        int u = t + j * 256;
        int row = u >> 3, ch = u & 7;
        cp16a(sK + swz(row * 128 + ch * 16), Kg + (size_t)row * DHEAD + ch * 8);
    }
    int qt0 = kt >> 1;
    issueQ(qt0, 0); cp_commit(); cp_wait<0>(); __syncthreads();

    uint32_t aOffU = (uint32_t)(wm * 32 + aRow) * 128 + aK16;
    uint32_t bOffU = (uint32_t)(wn * 32 + bRow) * 128 + bK16;

    // log2-domain constants
    float cb[4][2];   // kg * S2LOG  (fixed per thread)
#pragma unroll
    for (int nj = 0; nj < 4; nj++) {
        int kg = kt * 64 + wn * 32 + nj * 8 + 2 * tt;
        cb[nj][0] = (float)kg * S2LOG;
        cb[nj][1] = (float)(kg + 1) * S2LOG;
    }
    float qv[2][2];   // q * S2LOG for rows (mi, rh); updated per iteration
#pragma unroll
    for (int mi = 0; mi < 2; mi++)
#pragma unroll
        for (int rh = 0; rh < 2; rh++)
            qv[mi][rh] = (float)(qt0 * 128 + wm * 32 + mi * 16 + gg + rh * 8) * S2LOG;
    const float QSTEP = 128.0f * S2LOG;

    float part[4][2];
#pragma unroll
    for (int nj = 0; nj < 4; nj++) { part[nj][0] = 0.0f; part[nj][1] = 0.0f; }

#pragma unroll 1
    for (int qt = qt0; qt < SEQ / 128; qt++) {
        int it = qt - qt0;
        if (qt + 1 < SEQ / 128) { issueQ(qt + 1, (it + 1) & 1); cp_commit(); }

        uint32_t baQ = sQ + (it & 1) * 16384;
        float acc[2][4][4];
#pragma unroll
        for (int mi = 0; mi < 2; mi++)
#pragma unroll
            for (int nj = 0; nj < 4; nj++)
#pragma unroll
                for (int e = 0; e < 4; e++) acc[mi][nj][e] = 0.0f;

#pragma unroll
        for (int slab = 0; slab < 4; slab++) {
            uint32_t a[2][4], b[2][4];
            ldsm4(a[0], baQ + swz(aOffU + slab * 32));
            ldsm4(a[1], baQ + swz(aOffU + 2048 + slab * 32));
            ldsm4(b[0], sK + swz(bOffU + slab * 32));
            ldsm4(b[1], sK + swz(bOffU + 2048 + slab * 32));
#pragma unroll
            for (int mi = 0; mi < 2; mi++)
#pragma unroll
                for (int nj = 0; nj < 4; nj++)
                    mma16h(acc[mi][nj], a[mi], &b[nj >> 1][(nj & 1) * 2]);
        }

        if (it == 0) {
            // masked path: exact integer compares, only iteration with masks
            int q0 = qt * 128;
#pragma unroll
            for (int mi = 0; mi < 2; mi++) {
                int row = wm * 32 + mi * 16 + gg;
                int q = q0 + row;
#pragma unroll
                for (int nj = 0; nj < 4; nj++) {
                    int kl = wn * 32 + nj * 8 + 2 * tt;
                    int kg = kt * 64 + kl;
                    float v0 = (kg     <= q) ? ex2f(fmaf(acc[mi][nj][0], S2LOG, cb[nj][0]) - qv[mi][0]) : 0.0f;
                    float v1 = (kg + 1 <= q) ? ex2f(fmaf(acc[mi][nj][1], S2LOG, cb[nj][1]) - qv[mi][0]) : 0.0f;
                    float v2 = (kg     <= q + 8) ? ex2f(fmaf(acc[mi][nj][2], S2LOG, cb[nj][0]) - qv[mi][1]) : 0.0f;
                    float v3 = (kg + 1 <= q + 8) ? ex2f(fmaf(acc[mi][nj][3], S2LOG, cb[nj][1]) - qv[mi][1]) : 0.0f;
                    part[nj][0] += v0 + v2;
                    part[nj][1] += v1 + v3;
                    *(__half2*)&Pb[(size_t)q * SEQ + kl] = __floats2half2_rn(v0, v1);
                    *(__half2*)&Pb[(size_t)(q + 8) * SEQ + kl] = __floats2half2_rn(v2, v3);
                }
            }
        } else {
            // mask-free path (q >= all stripe columns)
            int q0 = qt * 128;
#pragma unroll
            for (int mi = 0; mi < 2; mi++) {
                int q = q0 + wm * 32 + mi * 16 + gg;
#pragma unroll
                for (int nj = 0; nj < 4; nj++) {
                    int kl = wn * 32 + nj * 8 + 2 * tt;
                    float v0 = ex2f(fmaf(acc[mi][nj][0], S2LOG, cb[nj][0]) - qv[mi][0]);
                    float v1 = ex2f(fmaf(acc[mi][nj][1], S2LOG, cb[nj][1]) - qv[mi][0]);
                    float v2 = ex2f(fmaf(acc[mi][nj][2], S2LOG, cb[nj][0]) - qv[mi][1]);
                    float v3 = ex2f(fmaf(acc[mi][nj][3], S2LOG, cb[nj][1]) - qv[mi][1]);
                    part[nj][0] += v0 + v2;
                    part[nj][1] += v1 + v3;
                    *(__half2*)&Pb[(size_t)q * SEQ + kl] = __floats2half2_rn(v0, v1);
                    *(__half2*)&Pb[(size_t)(q + 8) * SEQ + kl] = __floats2half2_rn(v2, v3);
                }
            }
        }
#pragma unroll
        for (int mi = 0; mi < 2; mi++) {
            qv[mi][0] += QSTEP;
            qv[mi][1] += QSTEP;
        }
        cp_wait<0>(); __syncthreads();
    }

#pragma unroll
    for (int nj = 0; nj < 4; nj++)
#pragma unroll
        for (int p = 0; p < 2; p++) {
            float v = part[nj][p];
            v += __shfl_xor_sync(0xffffffffu, v, 4);
            v += __shfl_xor_sync(0xffffffffu, v, 8);
            v += __shfl_xor_sync(0xffffffffu, v, 16);
            part[nj][p] = v;
        }
    if (lane < 4) {
#pragma unroll
        for (int nj = 0; nj < 4; nj++) {
            colsum[wm][wn * 32 + nj * 8 + 2 * lane]     = part[nj][0];
            colsum[wm][wn * 32 + nj * 8 + 2 * lane + 1] = part[nj][1];
        }
    }
    __syncthreads();
    if (t < 64)
        invs[t] = 1.0f / (colsum[0][t] + colsum[1][t] + colsum[2][t] + colsum[3][t]);
    __syncthreads();

    // scale + transpose fp16 V stripe -> g_Vt (staging pitch 65)
    const __half* Vg = g_Vh + ((size_t)bh * SEQ + kt * 64) * DHEAD;
#pragma unroll
    for (int j = 0; j < 2; j++) {
        int u = t + j * 256;                 // 512 x 16B covers 64x64 halves
        int r = u >> 3, e8 = (u & 7) * 8;
        uint4 raw = *(const uint4*)&Vg[(size_t)r * DHEAD + e8];
        float iv = invs[r];
        __half2 h0 = *(__half2*)&raw.x, h1 = *(__half2*)&raw.y;
        __half2 h2 = *(__half2*)&raw.z, h3 = *(__half2*)&raw.w;
        Vstage[r * 65 + e8 + 0] = __low2float(h0) * iv;
        Vstage[r * 65 + e8 + 1] = __high2float(h0) * iv;
        Vstage[r * 65 + e8 + 2] = __low2float(h1) * iv;
        Vstage[r * 65 + e8 + 3] = __high2float(h1) * iv;
        Vstage[r * 65 + e8 + 4] = __low2float(h2) * iv;
        Vstage[r * 65 + e8 + 5] = __high2float(h2) * iv;
        Vstage[r * 65 + e8 + 6] = __low2float(h3) * iv;
        Vstage[r * 65 + e8 + 7] = __high2float(h3) * iv;
    }
    __syncthreads();
    __half* Vt = g_Vt + (size_t)bh * DHEAD * SEQ + kt * 64;
#pragma unroll
    for (int er = 0; er < 8; er++) {
        int e = wid * 8 + er;
#pragma unroll
        for (int half_ = 0; half_ < 2; half_++) {
            int r = lane + half_ * 32;
            Vt[(size_t)e * SEQ + r] = __float2half_rn(Vstage[r * 65 + e]);
        }
    }
}

// ---------------------------------------------------------------------------
// pv_kernel (fp16): Ocat[128q x 64e] = P @ Vt^T, BK=64, 3-stage, occupancy 3.
// ---------------------------------------------------------------------------
__global__ __launch_bounds__(256, 3) void pv_kernel() {
    int qt = (int)gridDim.x - 1 - blockIdx.x;
    int bh = blockIdx.y;
    int b = bh >> 4, h = bh & 15;

    extern __shared__ float smf[];
    uint32_t sP = smem_u32(smf);                 // [3][128 x 128B] = 48KB
    uint32_t sV = sP + 3 * 16384;                // [3][64 x 128B]  = 24KB

    int t = threadIdx.x, wid = t >> 5;
    int wm = wid & 3, wn = wid >> 2;
    LANE_OFFS();

    const __half* Pg = g_Ph + ((size_t)bh * SEQ + qt * 128) * SEQ;
    const __half* Vtg = g_Vt + (size_t)bh * DHEAD * SEQ;

    float acc[2][4][4];
#pragma unroll
    for (int mi = 0; mi < 2; mi++)
#pragma unroll
        for (int nj = 0; nj < 4; nj++)
#pragma unroll
            for (int e = 0; e < 4; e++) acc[mi][nj][e] = 0.0f;

    int niter = 2 * qt + 2;

    auto issue = [&](int it3) {
        int s = it3 % 3;
        uint32_t bP = sP + s * 16384;
#pragma unroll
        for (int j = 0; j < 4; j++) {
            int u = t + j * 256;
            int row = u >> 3, ch = u & 7;
            cp16a(bP + swz(row * 128 + ch * 16), Pg + (size_t)row * SEQ + it3 * 64 + ch * 8);
        }
        uint32_t bV = sV + s * 8192;
#pragma unroll
        for (int j = 0; j < 2; j++) {
            int u = t + j * 256;
            int row = u >> 3, ch = u & 7;
            cp16a(bV + swz(row * 128 + ch * 16), Vtg + (size_t)row * SEQ + it3 * 64 + ch * 8);
        }
    };

    uint32_t aOffU = (uint32_t)(wm * 32 + aRow) * 128 + aK16;
    uint32_t bOffU = (uint32_t)(wn * 32 + bRow) * 128 + bK16;

    issue(0); cp_commit();
    if (niter > 1) { issue(1); cp_commit(); }
#pragma unroll 1
    for (int it = 0; it < niter; it++) {
        if (it + 1 < niter) cp_wait<1>(); else cp_wait<0>();
        __syncthreads();
        uint32_t bP = sP + (it % 3) * 16384;
        uint32_t bV = sV + (it % 3) * 8192;
#pragma unroll
        for (int slab = 0; slab < 4; slab++) {
            uint32_t a[2][4], bfr[2][4];
            ldsm4(a[0], bP + swz(aOffU + slab * 32));
            ldsm4(a[1], bP + swz(aOffU + 2048 + slab * 32));
            ldsm4(bfr[0], bV + swz(bOffU + slab * 32));
            ldsm4(bfr[1], bV + swz(bOffU + 2048 + slab * 32));
#pragma unroll
            for (int mi = 0; mi < 2; mi++)
#pragma unroll
                for (int nj = 0; nj < 4; nj++)
                    mma16h(acc[mi][nj], a[mi], &bfr[nj >> 1][(nj & 1) * 2]);
        }
        if (it + 2 < niter) { issue(it + 2); cp_commit(); }
    }

#pragma unroll
    for (int mi = 0; mi < 2; mi++) {
        int row = qt * 128 + wm * 32 + mi * 16 + gg;
#pragma unroll
        for (int nj = 0; nj < 4; nj++) {
            int colL = wn * 32 + nj * 8 + 2 * tt;
            __half* d0 = g_Ocat + ((size_t)(b * SEQ) + row) * DMODEL + h * 64 + colL;
            *(__half2*)d0 = __floats2half2_rn(acc[mi][nj][0], acc[mi][nj][1]);
            *(__half2*)(d0 + 8 * DMODEL) = __floats2half2_rn(acc[mi][nj][2], acc[mi][nj][3]);
        }
    }
}

// ---------------------------------------------------------------------------
// Launch. Inputs: keys, queries, values, WQ, WK, WV, WO, masking
// ---------------------------------------------------------------------------
extern "C" void kernel_launch(void* const* d_in, const int* in_sizes, int n_in,
                              void* d_out, int out_size) {
    const float* keys    = (const float*)d_in[0];
    const float* queries = (const float*)d_in[1];
    const float* values  = (const float*)d_in[2];
    const float* WQ      = (const float*)d_in[3];
    const float* WK      = (const float*)d_in[4];
    const float* WV      = (const float*)d_in[5];
    const float* WO      = (const float*)d_in[6];
    float* out = (float*)d_out;
    (void)in_sizes; (void)n_in; (void)out_size;

    const int projSmem = 3 * 8192 + 3 * 16384;                // 73728
    const int outSmem  = 3 * 16384 * 2;                       // 98304
    const int denSmem  = 8192 + 2 * 16384 + 64 * 65 * 4;      // 57600
    const int pvSmem   = 3 * 16384 + 3 * 8192;                // 73728
    cudaFuncSetAttribute(proj_kernel, cudaFuncAttributeMaxDynamicSharedMemorySize, projSmem);
    cudaFuncSetAttribute(out_kernel,  cudaFuncAttributeMaxDynamicSharedMemorySize, outSmem);
    cudaFuncSetAttribute(den_kernel,  cudaFuncAttributeMaxDynamicSharedMemorySize, denSmem);
    cudaFuncSetAttribute(pv_kernel,   cudaFuncAttributeMaxDynamicSharedMemorySize, pvSmem);

    // prologue (all fp16)
    xprep_kernel<<<dim3(MROWS * DMODEL / 4 / 256, 1, 3), 256>>>(
        (const float4*)queries, (const float4*)keys, (const float4*)values);
    wprep_kernel<<<dim3(DMODEL / 64, 16, 4), 256>>>(WQ, WK, WV, WO);

    // projections, fine-grain tiles (z=0 Q, z=1 K, z=2 V)
    proj_kernel<<<dim3(MROWS / 64, DMODEL / 128, 3), 256, projSmem>>>();

    // attention (fp16)
    den_kernel<<<dim3(SEQ / 64, BH), 256, denSmem>>>();
    pv_kernel<<<dim3(SEQ / 128, BH), 256, pvSmem>>>();

    // output projection (fp16)
    out_kernel<<<dim3(MROWS / 128, DMODEL / 128), 256, outSmem>>>(out);
}

// round 16
// speedup vs baseline: 1.1953x; 1.0302x over previous
#include <cuda_runtime.h>
#include <cuda_fp16.h>
#include <cstdint>
#include <cstddef>

#define BATCH  2
#define SEQ    2048
#define DMODEL 1024
#define NHEAD  16
#define DHEAD  64
#define BH     (BATCH*NHEAD)
#define MROWS  (BATCH*SEQ)
#define SCALE  0.022097086912079608f   // 1/sqrt(2048)
#define S2LOG  0.031883924137085614f   // SCALE * log2(e)

// ---------------- scratch (device globals; allocation-free rule) -----------
__device__ __align__(16) __half g_Xh[(size_t)3 * MROWS * DMODEL];    // fp16 q/k/v inputs
__device__ __align__(16) __half g_Wth[(size_t)3 * DMODEL * DMODEL];  // fp16 n-major WQ/WK/WV
__device__ __align__(16) __half g_WOth[(size_t)DMODEL * DMODEL];     // fp16 n-major WO
__device__ __align__(16) __half g_Qh[(size_t)BH * SEQ * DHEAD];
__device__ __align__(16) __half g_Kh[(size_t)BH * SEQ * DHEAD];
__device__ __align__(16) __half g_Vh[(size_t)BH * SEQ * DHEAD];
__device__ __align__(16) __half g_Vt[(size_t)BH * DHEAD * SEQ];      // [bh][e][k], scaled 1/den
__device__ __align__(16) __half g_Ph[(size_t)BH * SEQ * SEQ];        // exp(scores) fp16
__device__ __align__(16) __half g_Ocat[(size_t)MROWS * DMODEL];      // fp16 attention output

// ---------------- helpers ---------------------------------------------------
__device__ __forceinline__ uint32_t swz(uint32_t o) { return o ^ ((o >> 3) & 0x70); }
__device__ __forceinline__ uint32_t smem_u32(const void* p) {
    return (uint32_t)__cvta_generic_to_shared(p);
}
__device__ __forceinline__ void cp16a(uint32_t saddr, const void* gmem) {
    asm volatile("cp.async.cg.shared.global [%0], [%1], 16;" :: "r"(saddr), "l"(gmem));
}
__device__ __forceinline__ void cp_commit() { asm volatile("cp.async.commit_group;"); }
template <int N> __device__ __forceinline__ void cp_wait() {
    asm volatile("cp.async.wait_group %0;" :: "n"(N));
}
__device__ __forceinline__ void ldsm4(uint32_t (&r)[4], uint32_t saddr) {
    asm volatile("ldmatrix.sync.aligned.m8n8.x4.shared.b16 {%0,%1,%2,%3}, [%4];"
                 : "=r"(r[0]), "=r"(r[1]), "=r"(r[2]), "=r"(r[3]) : "r"(saddr));
}
__device__ __forceinline__ void mma16h(float (&c)[4], const uint32_t (&a)[4], const uint32_t* b) {
    asm volatile(
        "mma.sync.aligned.m16n8k16.row.col.f32.f16.f16.f32 "
        "{%0,%1,%2,%3}, {%4,%5,%6,%7}, {%8,%9}, {%0,%1,%2,%3};"
        : "+f"(c[0]), "+f"(c[1]), "+f"(c[2]), "+f"(c[3])
        : "r"(a[0]), "r"(a[1]), "r"(a[2]), "r"(a[3]), "r"(b[0]), "r"(b[1]));
}
__device__ __forceinline__ float ex2f(float x) {
    float r;
    asm("ex2.approx.f32 %0, %1;" : "=f"(r) : "f"(x));
    return r;
}
#define LANE_OFFS() \
    int lane = threadIdx.x & 31; \
    int aRow = ((lane >> 3) & 1) * 8 + (lane & 7); \
    int aK16 = (lane >> 4) * 16; \
    int bRow = (lane >> 4) * 8 + (lane & 7); \
    int bK16 = ((lane >> 3) & 1) * 16; \
    int gg = lane >> 2, tt = lane & 3; (void)gg; (void)tt;

// ---------------------------------------------------------------------------
// Prologue: queries/keys/values -> fp16
// ---------------------------------------------------------------------------
__global__ __launch_bounds__(256) void xprep_kernel(const float4* __restrict__ q,
                                                    const float4* __restrict__ k,
                                                    const float4* __restrict__ v) {
    int which = blockIdx.z;
    const float4* src = (which == 0) ? q : (which == 1) ? k : v;
    size_t i = (size_t)blockIdx.x * 256 + threadIdx.x;
    float4 x = src[i];
    __half* dst = g_Xh + (size_t)which * MROWS * DMODEL + i * 4;
    *(__half2*)dst = __floats2half2_rn(x.x, x.y);
    *(__half2*)(dst + 2) = __floats2half2_rn(x.z, x.w);
}

// z<3: W[h][d][e] -> fp16 n-major [h*64+e][d]; z==3: WO[d][c] -> fp16 [c][d]
__global__ __launch_bounds__(256) void wprep_kernel(const float* __restrict__ WQ,
                                                    const float* __restrict__ WK,
                                                    const float* __restrict__ WV,
                                                    const float* __restrict__ WO) {
    int which = blockIdx.z;
    __shared__ float tile[64 * 65];
    int t = threadIdx.x;
    if (which < 3) {
        int h = blockIdx.y, d0 = blockIdx.x * 64;
        const float* W = ((which == 0) ? WQ : (which == 1) ? WK : WV)
                         + ((size_t)h * DMODEL + d0) * DHEAD;
#pragma unroll
        for (int j = 0; j < 16; j++) {
            int u = t + j * 256;
            tile[(u >> 6) * 65 + (u & 63)] = W[(size_t)(u >> 6) * DHEAD + (u & 63)];
        }
        __syncthreads();
        __half* out = g_Wth + (size_t)which * DMODEL * DMODEL + (size_t)h * 64 * DMODEL + d0;
#pragma unroll
        for (int j = 0; j < 16; j++) {
            int u = t + j * 256;
            int e = u >> 6, dc = u & 63;
            out[(size_t)e * DMODEL + dc] = __float2half_rn(tile[dc * 65 + e]);
        }
    } else {
        int d0 = blockIdx.x * 64, c0 = blockIdx.y * 64;
#pragma unroll
        for (int j = 0; j < 16; j++) {
            int u = t + j * 256;
            tile[(u >> 6) * 65 + (u & 63)] = WO[(size_t)(d0 + (u >> 6)) * DMODEL + c0 + (u & 63)];
        }
        __syncthreads();
#pragma unroll
        for (int j = 0; j < 16; j++) {
            int u = t + j * 256;
            int cr = u >> 6, dc = u & 63;
            g_WOth[(size_t)(c0 + cr) * DMODEL + d0 + dc] = __float2half_rn(tile[dc * 65 + cr]);
        }
    }
}

// ---------------------------------------------------------------------------
// proj_kernel: all three projections, fp16, BM=64 x BN=128 tiles, 2x4 warps ->
// warp 32x32, BK=64, 3-stage, single-sync, occupancy 3. z -> g_Qh/g_Kh/g_Vh.
// ---------------------------------------------------------------------------
__global__ __launch_bounds__(256, 3) void proj_kernel() {
    extern __shared__ float smf[];
    uint32_t sA = smem_u32(smf);           // [3][64 x 128B]  = 24KB
    uint32_t sB = sA + 3 * 8192;           // [3][128 x 128B] = 48KB

    int t = threadIdx.x, wid = t >> 5;
    int wm = wid & 1, wn = wid >> 1;       // 2x4 warps -> 64x128, warp 32x32
    int m0 = blockIdx.x * 64, n0 = blockIdx.y * 128, which = blockIdx.z;
    LANE_OFFS();

    const __half* A = g_Xh + (size_t)which * MROWS * DMODEL + (size_t)m0 * DMODEL;
    const __half* B = g_Wth + (size_t)which * DMODEL * DMODEL + (size_t)n0 * DMODEL;

    uint32_t aOffU = (uint32_t)(wm * 32 + aRow) * 128 + aK16;
    uint32_t bOffU = (uint32_t)(wn * 32 + bRow) * 128 + bK16;

    float acc[2][4][4];
#pragma unroll
    for (int mi = 0; mi < 2; mi++)
#pragma unroll
        for (int nj = 0; nj < 4; nj++)
#pragma unroll
            for (int e = 0; e < 4; e++) acc[mi][nj][e] = 0.0f;

    auto issue = [&](int it3) {
        int s = it3 % 3;
        int kk = it3 * 64;
        uint32_t bA = sA + s * 8192;
        uint32_t bB = sB + s * 16384;
#pragma unroll
        for (int j = 0; j < 2; j++) {          // A: 64 rows x 128B
            int u = t + j * 256;
            int row = u >> 3, ch = u & 7;
            cp16a(bA + swz(row * 128 + ch * 16), A + (size_t)row * DMODEL + kk + ch * 8);
        }
#pragma unroll
        for (int j = 0; j < 4; j++) {          // B: 128 rows x 128B
            int u = t + j * 256;
            int row = u >> 3, ch = u & 7;
            cp16a(bB + swz(row * 128 + ch * 16), B + (size_t)row * DMODEL + kk + ch * 8);
        }
    };

    issue(0); cp_commit();
    issue(1); cp_commit();
#pragma unroll 1
    for (int it = 0; it < 16; it++) {
        if (it < 15) cp_wait<1>(); else cp_wait<0>();
        __syncthreads();
        uint32_t bA = sA + (it % 3) * 8192;
        uint32_t bB = sB + (it % 3) * 16384;
#pragma unroll
        for (int slab = 0; slab < 4; slab++) {
            uint32_t a[2][4], b[2][4];
            ldsm4(a[0], bA + swz(aOffU + slab * 32));
            ldsm4(a[1], bA + swz(aOffU + 2048 + slab * 32));
            ldsm4(b[0], bB + swz(bOffU + slab * 32));
            ldsm4(b[1], bB + swz(bOffU + 2048 + slab * 32));
#pragma unroll
            for (int mi = 0; mi < 2; mi++)
#pragma unroll
                for (int nj = 0; nj < 4; nj++)
                    mma16h(acc[mi][nj], a[mi], &b[nj >> 1][(nj & 1) * 2]);
        }
        if (it + 2 < 16) { issue(it + 2); cp_commit(); }
    }

    __half* Outp = (which == 0) ? g_Qh : (which == 1) ? g_Kh : g_Vh;
#pragma unroll
    for (int mi = 0; mi < 2; mi++) {
        int mrow = m0 + wm * 32 + mi * 16 + gg;
#pragma unroll
        for (int nj = 0; nj < 4; nj++) {
            int col = n0 + wn * 32 + nj * 8 + 2 * tt;
            int b = mrow >> 11, s = mrow & (SEQ - 1);
            int h = col >> 6, e = col & 63;
            __half* dst = Outp + ((size_t)(b * NHEAD + h) * SEQ + s) * DHEAD + e;
            *(__half2*)dst = __floats2half2_rn(acc[mi][nj][0], acc[mi][nj][1]);
            *(__half2*)(dst + 8 * DHEAD) = __floats2half2_rn(acc[mi][nj][2], acc[mi][nj][3]);
        }
    }
}

// ---------------------------------------------------------------------------
// out_kernel (fp16, proj-style 64x128 tiles, BK=64, 3-stage, occupancy 3):
// Out = Ocat @ WOt^T -> fp32.
// ---------------------------------------------------------------------------
__global__ __launch_bounds__(256, 3) void out_kernel(float* __restrict__ Cout) {
    extern __shared__ float smf[];
    uint32_t sA = smem_u32(smf);           // [3][64 x 128B]  = 24KB
    uint32_t sB = sA + 3 * 8192;           // [3][128 x 128B] = 48KB

    int t = threadIdx.x, wid = t >> 5;
    int wm = wid & 1, wn = wid >> 1;       // 2x4 warps -> 64x128, warp 32x32
    int m0 = blockIdx.x * 64, n0 = blockIdx.y * 128;
    LANE_OFFS();

    const __half* A = g_Ocat + (size_t)m0 * DMODEL;
    const __half* B = g_WOth + (size_t)n0 * DMODEL;

    uint32_t aOffU = (uint32_t)(wm * 32 + aRow) * 128 + aK16;
    uint32_t bOffU = (uint32_t)(wn * 32 + bRow) * 128 + bK16;

    float acc[2][4][4];
#pragma unroll
    for (int mi = 0; mi < 2; mi++)
#pragma unroll
        for (int nj = 0; nj < 4; nj++)
#pragma unroll
            for (int e = 0; e < 4; e++) acc[mi][nj][e] = 0.0f;

    auto issue = [&](int it3) {
        int s = it3 % 3;
        int kk = it3 * 64;
        uint32_t bA = sA + s * 8192;
        uint32_t bB = sB + s * 16384;
#pragma unroll
        for (int j = 0; j < 2; j++) {
            int u = t + j * 256;
            int row = u >> 3, ch = u & 7;
            cp16a(bA + swz(row * 128 + ch * 16), A + (size_t)row * DMODEL + kk + ch * 8);
        }
#pragma unroll
        for (int j = 0; j < 4; j++) {
            int u = t + j * 256;
            int row = u >> 3, ch = u & 7;
            cp16a(bB + swz(row * 128 + ch * 16), B + (size_t)row * DMODEL + kk + ch * 8);
        }
    };

    issue(0); cp_commit();
    issue(1); cp_commit();
#pragma unroll 1
    for (int it = 0; it < 16; it++) {
        if (it < 15) cp_wait<1>(); else cp_wait<0>();
        __syncthreads();
        uint32_t bA = sA + (it % 3) * 8192;
        uint32_t bB = sB + (it % 3) * 16384;
#pragma unroll
        for (int slab = 0; slab < 4; slab++) {
            uint32_t a[2][4], b[2][4];
            ldsm4(a[0], bA + swz(aOffU + slab * 32));
            ldsm4(a[1], bA + swz(aOffU + 2048 + slab * 32));
            ldsm4(b[0], bB + swz(bOffU + slab * 32));
            ldsm4(b[1], bB + swz(bOffU + 2048 + slab * 32));
#pragma unroll
            for (int mi = 0; mi < 2; mi++)
#pragma unroll
                for (int nj = 0; nj < 4; nj++)
                    mma16h(acc[mi][nj], a[mi], &b[nj >> 1][(nj & 1) * 2]);
        }
        if (it + 2 < 16) { issue(it + 2); cp_commit(); }
    }

#pragma unroll
    for (int mi = 0; mi < 2; mi++) {
        int mrow = m0 + wm * 32 + mi * 16 + gg;
#pragma unroll
        for (int nj = 0; nj < 4; nj++) {
            int col = n0 + wn * 32 + nj * 8 + 2 * tt;
            float* d0 = Cout + (size_t)mrow * DMODEL + col;
            *(float2*)d0 = make_float2(acc[mi][nj][0], acc[mi][nj][1]);
            *(float2*)(d0 + 8 * DMODEL) = make_float2(acc[mi][nj][2], acc[mi][nj][3]);
        }
    }
}

// ---------------------------------------------------------------------------
// den_kernel (128q x 64k stripes): S = Q K^T; P = exp (log2-domain ex2,
// masking only on iter 0). P tile staged in smem and written as coalesced
// 128B rows (halves store sector traffic). Colsums in registers; fp16 V
// stripe scaled + transposed -> g_Vt (Vstage aliases the P staging buffer).
// ---------------------------------------------------------------------------
#define PSTAGE_PITCH 72   // halves; 144B rows -> conflict-free half2 writes
__global__ __launch_bounds__(256, 2) void den_kernel() {
    int kt = blockIdx.x;          // kt=0 heaviest first
    int bh = blockIdx.y;

    extern __shared__ float smf[];
    uint32_t sK = smem_u32(smf);                 // fp16 K stripe: 8KB
    uint32_t sQ = sK + 8192;                     // fp16 Q tiles: 2 x 16KB
    __half* Pstage = (__half*)((char*)smf + 8192 + 32768);  // [128][72] fp16 = 18KB
    float* Vstage = (float*)Pstage;              // [64][65] fp32 (aliases, used at end)
    __shared__ float colsum[4][64];
    __shared__ float invs[64];

    int t = threadIdx.x, wid = t >> 5;
    int wm = wid & 3, wn = wid >> 2;             // 4x2 warps -> 128q x 64k
    LANE_OFFS();

    const __half* Qg = g_Qh + (size_t)bh * SEQ * DHEAD;
    const __half* Kg = g_Kh + ((size_t)bh * SEQ + kt * 64) * DHEAD;
    __half* Pb = g_Ph + (size_t)bh * SEQ * SEQ + kt * 64;

    auto issueQ = [&](int qt, int s) {
        const __half* src = Qg + (size_t)qt * 128 * DHEAD;
        uint32_t base = sQ + s * 16384;
#pragma unroll
        for (int j = 0; j < 4; j++) {
            int u = t + j * 256;
            int row = u >> 3, ch = u & 7;
            cp16a(base + swz(row * 128 + ch * 16), src + (size_t)row * DHEAD + ch * 8);
        }
    };

#pragma unroll
    for (int j = 0; j < 2; j++) {
        int u = t + j * 256;
        int row = u >> 3, ch = u & 7;
        cp16a(sK + swz(row * 128 + ch * 16), Kg + (size_t)row * DHEAD + ch * 8);
    }
    int qt0 = kt >> 1;
    issueQ(qt0, 0); cp_commit(); cp_wait<0>(); __syncthreads();

    uint32_t aOffU = (uint32_t)(wm * 32 + aRow) * 128 + aK16;
    uint32_t bOffU = (uint32_t)(wn * 32 + bRow) * 128 + bK16;

    // log2-domain constants
    float cb[4][2];
#pragma unroll
    for (int nj = 0; nj < 4; nj++) {
        int kg = kt * 64 + wn * 32 + nj * 8 + 2 * tt;
        cb[nj][0] = (float)kg * S2LOG;
        cb[nj][1] = (float)(kg + 1) * S2LOG;
    }
    float qv[2][2];
#pragma unroll
    for (int mi = 0; mi < 2; mi++)
#pragma unroll
        for (int rh = 0; rh < 2; rh++)
            qv[mi][rh] = (float)(qt0 * 128 + wm * 32 + mi * 16 + gg + rh * 8) * S2LOG;
    const float QSTEP = 128.0f * S2LOG;

    float part[4][2];
#pragma unroll
    for (int nj = 0; nj < 4; nj++) { part[nj][0] = 0.0f; part[nj][1] = 0.0f; }

#pragma unroll 1
    for (int qt = qt0; qt < SEQ / 128; qt++) {
        int it = qt - qt0;
        if (qt + 1 < SEQ / 128) { issueQ(qt + 1, (it + 1) & 1); cp_commit(); }

        uint32_t baQ = sQ + (it & 1) * 16384;
        float acc[2][4][4];
#pragma unroll
        for (int mi = 0; mi < 2; mi++)
#pragma unroll
            for (int nj = 0; nj < 4; nj++)
#pragma unroll
                for (int e = 0; e < 4; e++) acc[mi][nj][e] = 0.0f;

#pragma unroll
        for (int slab = 0; slab < 4; slab++) {
            uint32_t a[2][4], b[2][4];
            ldsm4(a[0], baQ + swz(aOffU + slab * 32));
            ldsm4(a[1], baQ + swz(aOffU + 2048 + slab * 32));
            ldsm4(b[0], sK + swz(bOffU + slab * 32));
            ldsm4(b[1], sK + swz(bOffU + 2048 + slab * 32));
#pragma unroll
            for (int mi = 0; mi < 2; mi++)
#pragma unroll
                for (int nj = 0; nj < 4; nj++)
                    mma16h(acc[mi][nj], a[mi], &b[nj >> 1][(nj & 1) * 2]);
        }

        if (it == 0) {
            // masked epilogue (only iteration with masked entries)
#pragma unroll
            for (int mi = 0; mi < 2; mi++) {
                int row = wm * 32 + mi * 16 + gg;
                int q = qt * 128 + row;
#pragma unroll
                for (int nj = 0; nj < 4; nj++) {
                    int kl = wn * 32 + nj * 8 + 2 * tt;
                    int kg = kt * 64 + kl;
                    float v0 = (kg     <= q) ? ex2f(fmaf(acc[mi][nj][0], S2LOG, cb[nj][0]) - qv[mi][0]) : 0.0f;
                    float v1 = (kg + 1 <= q) ? ex2f(fmaf(acc[mi][nj][1], S2LOG, cb[nj][1]) - qv[mi][0]) : 0.0f;
                    float v2 = (kg     <= q + 8) ? ex2f(fmaf(acc[mi][nj][2], S2LOG, cb[nj][0]) - qv[mi][1]) : 0.0f;
                    float v3 = (kg + 1 <= q + 8) ? ex2f(fmaf(acc[mi][nj][3], S2LOG, cb[nj][1]) - qv[mi][1]) : 0.0f;
                    part[nj][0] += v0 + v2;
                    part[nj][1] += v1 + v3;
                    *(__half2*)&Pstage[row * PSTAGE_PITCH + kl] = __floats2half2_rn(v0, v1);
                    *(__half2*)&Pstage[(row + 8) * PSTAGE_PITCH + kl] = __floats2half2_rn(v2, v3);
                }
            }
        } else {
            // mask-free epilogue
#pragma unroll
            for (int mi = 0; mi < 2; mi++) {
                int row = wm * 32 + mi * 16 + gg;
#pragma unroll
                for (int nj = 0; nj < 4; nj++) {
                    int kl = wn * 32 + nj * 8 + 2 * tt;
                    float v0 = ex2f(fmaf(acc[mi][nj][0], S2LOG, cb[nj][0]) - qv[mi][0]);
                    float v1 = ex2f(fmaf(acc[mi][nj][1], S2LOG, cb[nj][1]) - qv[mi][0]);
                    float v2 = ex2f(fmaf(acc[mi][nj][2], S2LOG, cb[nj][0]) - qv[mi][1]);
                    float v3 = ex2f(fmaf(acc[mi][nj][3], S2LOG, cb[nj][1]) - qv[mi][1]);
                    part[nj][0] += v0 + v2;
                    part[nj][1] += v1 + v3;
                    *(__half2*)&Pstage[row * PSTAGE_PITCH + kl] = __floats2half2_rn(v0, v1);
                    *(__half2*)&Pstage[(row + 8) * PSTAGE_PITCH + kl] = __floats2half2_rn(v2, v3);
                }
            }
        }
#pragma unroll
        for (int mi = 0; mi < 2; mi++) {
            qv[mi][0] += QSTEP;
            qv[mi][1] += QSTEP;
        }
        __syncthreads();                      // Pstage fully written

        // coalesced P write-out: 128 rows x 128B, STG.128 full lines
        {
            int q0 = qt * 128;
#pragma unroll
            for (int j = 0; j < 4; j++) {
                int c = t + j * 256;          // 1024 chunks of 16B
                int row = c >> 3, seg = c & 7;
                uint4 v = *(const uint4*)&Pstage[row * PSTAGE_PITCH + seg * 8];
                *(uint4*)&Pb[(size_t)(q0 + row) * SEQ + seg * 8] = v;
            }
        }
        cp_wait<0>(); __syncthreads();        // next Q ready; Pstage reusable
    }

#pragma unroll
    for (int nj = 0; nj < 4; nj++)
#pragma unroll
        for (int p = 0; p < 2; p++) {
            float v = part[nj][p];
            v += __shfl_xor_sync(0xffffffffu, v, 4);
            v += __shfl_xor_sync(0xffffffffu, v, 8);
            v += __shfl_xor_sync(0xffffffffu, v, 16);
            part[nj][p] = v;
        }
    if (lane < 4) {
#pragma unroll
        for (int nj = 0; nj < 4; nj++) {
            colsum[wm][wn * 32 + nj * 8 + 2 * lane]     = part[nj][0];
            colsum[wm][wn * 32 + nj * 8 + 2 * lane + 1] = part[nj][1];
        }
    }
    __syncthreads();
    if (t < 64)
        invs[t] = 1.0f / (colsum[0][t] + colsum[1][t] + colsum[2][t] + colsum[3][t]);
    __syncthreads();

    // scale + transpose fp16 V stripe -> g_Vt (Vstage aliases Pstage; pitch 65)
    const __half* Vg = g_Vh + ((size_t)bh * SEQ + kt * 64) * DHEAD;
#pragma unroll
    for (int j = 0; j < 2; j++) {
        int u = t + j * 256;                 // 512 x 16B covers 64x64 halves
        int r = u >> 3, e8 = (u & 7) * 8;
        uint4 raw = *(const uint4*)&Vg[(size_t)r * DHEAD + e8];
        float iv = invs[r];
        __half2 h0 = *(__half2*)&raw.x, h1 = *(__half2*)&raw.y;
        __half2 h2 = *(__half2*)&raw.z, h3 = *(__half2*)&raw.w;
        Vstage[r * 65 + e8 + 0] = __low2float(h0) * iv;
        Vstage[r * 65 + e8 + 1] = __high2float(h0) * iv;
        Vstage[r * 65 + e8 + 2] = __low2float(h1) * iv;
        Vstage[r * 65 + e8 + 3] = __high2float(h1) * iv;
        Vstage[r * 65 + e8 + 4] = __low2float(h2) * iv;
        Vstage[r * 65 + e8 + 5] = __high2float(h2) * iv;
        Vstage[r * 65 + e8 + 6] = __low2float(h3) * iv;
        Vstage[r * 65 + e8 + 7] = __high2float(h3) * iv;
    }
    __syncthreads();
    __half* Vt = g_Vt + (size_t)bh * DHEAD * SEQ + kt * 64;
#pragma unroll
    for (int er = 0; er < 8; er++) {
        int e = wid * 8 + er;
#pragma unroll
        for (int half_ = 0; half_ < 2; half_++) {
            int r = lane + half_ * 32;
            Vt[(size_t)e * SEQ + r] = __float2half_rn(Vstage[r * 65 + e]);
        }
    }
}

// ---------------------------------------------------------------------------
// pv_kernel (fp16): Ocat[128q x 64e] = P @ Vt^T, BK=64, 3-stage, occupancy 3.
// bh processed in REVERSE so the most recently den-written P is read first
// (L2 temporal locality).
// ---------------------------------------------------------------------------
__global__ __launch_bounds__(256, 3) void pv_kernel() {
    int qt = (int)gridDim.x - 1 - blockIdx.x;
    int bh = (int)gridDim.y - 1 - blockIdx.y;
    int b = bh >> 4, h = bh & 15;

    extern __shared__ float smf[];
    uint32_t sP = smem_u32(smf);                 // [3][128 x 128B] = 48KB
    uint32_t sV = sP + 3 * 16384;                // [3][64 x 128B]  = 24KB

    int t = threadIdx.x, wid = t >> 5;
    int wm = wid & 3, wn = wid >> 2;
    LANE_OFFS();

    const __half* Pg = g_Ph + ((size_t)bh * SEQ + qt * 128) * SEQ;
    const __half* Vtg = g_Vt + (size_t)bh * DHEAD * SEQ;

    float acc[2][4][4];
#pragma unroll
    for (int mi = 0; mi < 2; mi++)
#pragma unroll
        for (int nj = 0; nj < 4; nj++)
#pragma unroll
            for (int e = 0; e < 4; e++) acc[mi][nj][e] = 0.0f;

    int niter = 2 * qt + 2;

    auto issue = [&](int it3) {
        int s = it3 % 3;
        uint32_t bP = sP + s * 16384;
#pragma unroll
        for (int j = 0; j < 4; j++) {
            int u = t + j * 256;
            int row = u >> 3, ch = u & 7;
            cp16a(bP + swz(row * 128 + ch * 16), Pg + (size_t)row * SEQ + it3 * 64 + ch * 8);
        }
        uint32_t bV = sV + s * 8192;
#pragma unroll
        for (int j = 0; j < 2; j++) {
            int u = t + j * 256;
            int row = u >> 3, ch = u & 7;
            cp16a(bV + swz(row * 128 + ch * 16), Vtg + (size_t)row * SEQ + it3 * 64 + ch * 8);
        }
    };

    uint32_t aOffU = (uint32_t)(wm * 32 + aRow) * 128 + aK16;
    uint32_t bOffU = (uint32_t)(wn * 32 + bRow) * 128 + bK16;

    issue(0); cp_commit();
    if (niter > 1) { issue(1); cp_commit(); }
#pragma unroll 1
    for (int it = 0; it < niter; it++) {
        if (it + 1 < niter) cp_wait<1>(); else cp_wait<0>();
        __syncthreads();
        uint32_t bP = sP + (it % 3) * 16384;
        uint32_t bV = sV + (it % 3) * 8192;
#pragma unroll
        for (int slab = 0; slab < 4; slab++) {
            uint32_t a[2][4], bfr[2][4];
            ldsm4(a[0], bP + swz(aOffU + slab * 32));
            ldsm4(a[1], bP + swz(aOffU + 2048 + slab * 32));
            ldsm4(bfr[0], bV + swz(bOffU + slab * 32));
            ldsm4(bfr[1], bV + swz(bOffU + 2048 + slab * 32));
#pragma unroll
            for (int mi = 0; mi < 2; mi++)
#pragma unroll
                for (int nj = 0; nj < 4; nj++)
                    mma16h(acc[mi][nj], a[mi], &bfr[nj >> 1][(nj & 1) * 2]);
        }
        if (it + 2 < niter) { issue(it + 2); cp_commit(); }
    }

#pragma unroll
    for (int mi = 0; mi < 2; mi++) {
        int row = qt * 128 + wm * 32 + mi * 16 + gg;
#pragma unroll
        for (int nj = 0; nj < 4; nj++) {
            int colL = wn * 32 + nj * 8 + 2 * tt;
            __half* d0 = g_Ocat + ((size_t)(b * SEQ) + row) * DMODEL + h * 64 + colL;
            *(__half2*)d0 = __floats2half2_rn(acc[mi][nj][0], acc[mi][nj][1]);
            *(__half2*)(d0 + 8 * DMODEL) = __floats2half2_rn(acc[mi][nj][2], acc[mi][nj][3]);
        }
    }
}

// ---------------------------------------------------------------------------
// Launch. Inputs: keys, queries, values, WQ, WK, WV, WO, masking
// ---------------------------------------------------------------------------
extern "C" void kernel_launch(void* const* d_in, const int* in_sizes, int n_in,
                              void* d_out, int out_size) {
    const float* keys    = (const float*)d_in[0];
    const float* queries = (const float*)d_in[1];
    const float* values  = (const float*)d_in[2];
    const float* WQ      = (const float*)d_in[3];
    const float* WK      = (const float*)d_in[4];
    const float* WV      = (const float*)d_in[5];
    const float* WO      = (const float*)d_in[6];
    float* out = (float*)d_out;
    (void)in_sizes; (void)n_in; (void)out_size;

    const int projSmem = 3 * 8192 + 3 * 16384;                     // 73728
    const int outSmem  = 3 * 8192 + 3 * 16384;                     // 73728
    const int denSmem  = 8192 + 2 * 16384 + 128 * PSTAGE_PITCH * 2; // 59392
    const int pvSmem   = 3 * 16384 + 3 * 8192;                     // 73728
    cudaFuncSetAttribute(proj_kernel, cudaFuncAttributeMaxDynamicSharedMemorySize, projSmem);
    cudaFuncSetAttribute(out_kernel,  cudaFuncAttributeMaxDynamicSharedMemorySize, outSmem);
    cudaFuncSetAttribute(den_kernel,  cudaFuncAttributeMaxDynamicSharedMemorySize, denSmem);
    cudaFuncSetAttribute(pv_kernel,   cudaFuncAttributeMaxDynamicSharedMemorySize, pvSmem);

    // prologue (all fp16)
    xprep_kernel<<<dim3(MROWS * DMODEL / 4 / 256, 1, 3), 256>>>(
        (const float4*)queries, (const float4*)keys, (const float4*)values);
    wprep_kernel<<<dim3(DMODEL / 64, 16, 4), 256>>>(WQ, WK, WV, WO);

    // projections (z=0 Q, z=1 K, z=2 V)
    proj_kernel<<<dim3(MROWS / 64, DMODEL / 128, 3), 256, projSmem>>>();

    // attention (fp16)
    den_kernel<<<dim3(SEQ / 64, BH), 256, denSmem>>>();
    pv_kernel<<<dim3(SEQ / 128, BH), 256, pvSmem>>>();

    // output projection (fp16)
    out_kernel<<<dim3(MROWS / 64, DMODEL / 128), 256, outSmem>>>(out);
}

// round 17
// speedup vs baseline: 1.2262x; 1.0259x over previous
#include <cuda_runtime.h>
#include <cuda_fp16.h>
#include <cstdint>
#include <cstddef>

#define BATCH  2
#define SEQ    2048
#define DMODEL 1024
#define NHEAD  16
#define DHEAD  64
#define BH     (BATCH*NHEAD)
#define MROWS  (BATCH*SEQ)
#define SCALE  0.022097086912079608f   // 1/sqrt(2048)
#define S2LOG  0.031883924137085614f   // SCALE * log2(e)

// ---------------- scratch (device globals; allocation-free rule) -----------
__device__ __align__(16) __half g_Xh[(size_t)3 * MROWS * DMODEL];    // fp16 q/k/v inputs
__device__ __align__(16) __half g_Wth[(size_t)3 * DMODEL * DMODEL];  // fp16 n-major WQ/WK/WV
__device__ __align__(16) __half g_WOth[(size_t)DMODEL * DMODEL];     // fp16 n-major WO
__device__ __align__(16) __half g_Qh[(size_t)BH * SEQ * DHEAD];
__device__ __align__(16) __half g_Kh[(size_t)BH * SEQ * DHEAD];
__device__ __align__(16) __half g_Vh[(size_t)BH * SEQ * DHEAD];
__device__ __align__(16) __half g_Vt[(size_t)BH * DHEAD * SEQ];      // [bh][e][k], scaled 1/den
__device__ __align__(16) __half g_Ph[(size_t)BH * SEQ * SEQ];        // exp(scores) fp16
__device__ __align__(16) __half g_Ocat[(size_t)MROWS * DMODEL];      // fp16 attention output

// ---------------- helpers ---------------------------------------------------
__device__ __forceinline__ uint32_t swz(uint32_t o) { return o ^ ((o >> 3) & 0x70); }
__device__ __forceinline__ uint32_t smem_u32(const void* p) {
    return (uint32_t)__cvta_generic_to_shared(p);
}
__device__ __forceinline__ void cp16a(uint32_t saddr, const void* gmem) {
    asm volatile("cp.async.cg.shared.global [%0], [%1], 16;" :: "r"(saddr), "l"(gmem));
}
__device__ __forceinline__ void cp_commit() { asm volatile("cp.async.commit_group;"); }
template <int N> __device__ __forceinline__ void cp_wait() {
    asm volatile("cp.async.wait_group %0;" :: "n"(N));
}
__device__ __forceinline__ void ldsm4(uint32_t (&r)[4], uint32_t saddr) {
    asm volatile("ldmatrix.sync.aligned.m8n8.x4.shared.b16 {%0,%1,%2,%3}, [%4];"
                 : "=r"(r[0]), "=r"(r[1]), "=r"(r[2]), "=r"(r[3]) : "r"(saddr));
}
__device__ __forceinline__ void mma16h(float (&c)[4], const uint32_t (&a)[4], const uint32_t* b) {
    asm volatile(
        "mma.sync.aligned.m16n8k16.row.col.f32.f16.f16.f32 "
        "{%0,%1,%2,%3}, {%4,%5,%6,%7}, {%8,%9}, {%0,%1,%2,%3};"
        : "+f"(c[0]), "+f"(c[1]), "+f"(c[2]), "+f"(c[3])
        : "r"(a[0]), "r"(a[1]), "r"(a[2]), "r"(a[3]), "r"(b[0]), "r"(b[1]));
}
__device__ __forceinline__ float ex2f(float x) {
    float r;
    asm("ex2.approx.f32 %0, %1;" : "=f"(r) : "f"(x));
    return r;
}
__device__ __forceinline__ __half2 h2ex2(__half2 x) {
    uint32_t r, xi = *(uint32_t*)&x;
    asm("ex2.approx.f16x2 %0, %1;" : "=r"(r) : "r"(xi));
    return *(__half2*)&r;
}
#define LANE_OFFS() \
    int lane = threadIdx.x & 31; \
    int aRow = ((lane >> 3) & 1) * 8 + (lane & 7); \
    int aK16 = (lane >> 4) * 16; \
    int bRow = (lane >> 4) * 8 + (lane & 7); \
    int bK16 = ((lane >> 3) & 1) * 16; \
    int gg = lane >> 2, tt = lane & 3; (void)gg; (void)tt;

// ---------------------------------------------------------------------------
// Prologue: queries/keys/values -> fp16
// ---------------------------------------------------------------------------
__global__ __launch_bounds__(256) void xprep_kernel(const float4* __restrict__ q,
                                                    const float4* __restrict__ k,
                                                    const float4* __restrict__ v) {
    int which = blockIdx.z;
    const float4* src = (which == 0) ? q : (which == 1) ? k : v;
    size_t i = (size_t)blockIdx.x * 256 + threadIdx.x;
    float4 x = src[i];
    __half* dst = g_Xh + (size_t)which * MROWS * DMODEL + i * 4;
    *(__half2*)dst = __floats2half2_rn(x.x, x.y);
    *(__half2*)(dst + 2) = __floats2half2_rn(x.z, x.w);
}

// z<3: W[h][d][e] -> fp16 n-major [h*64+e][d]; z==3: WO[d][c] -> fp16 [c][d]
__global__ __launch_bounds__(256) void wprep_kernel(const float* __restrict__ WQ,
                                                    const float* __restrict__ WK,
                                                    const float* __restrict__ WV,
                                                    const float* __restrict__ WO) {
    int which = blockIdx.z;
    __shared__ float tile[64 * 65];
    int t = threadIdx.x;
    if (which < 3) {
        int h = blockIdx.y, d0 = blockIdx.x * 64;
        const float* W = ((which == 0) ? WQ : (which == 1) ? WK : WV)
                         + ((size_t)h * DMODEL + d0) * DHEAD;
#pragma unroll
        for (int j = 0; j < 16; j++) {
            int u = t + j * 256;
            tile[(u >> 6) * 65 + (u & 63)] = W[(size_t)(u >> 6) * DHEAD + (u & 63)];
        }
        __syncthreads();
        __half* out = g_Wth + (size_t)which * DMODEL * DMODEL + (size_t)h * 64 * DMODEL + d0;
#pragma unroll
        for (int j = 0; j < 16; j++) {
            int u = t + j * 256;
            int e = u >> 6, dc = u & 63;
            out[(size_t)e * DMODEL + dc] = __float2half_rn(tile[dc * 65 + e]);
        }
    } else {
        int d0 = blockIdx.x * 64, c0 = blockIdx.y * 64;
#pragma unroll
        for (int j = 0; j < 16; j++) {
            int u = t + j * 256;
            tile[(u >> 6) * 65 + (u & 63)] = WO[(size_t)(d0 + (u >> 6)) * DMODEL + c0 + (u & 63)];
        }
        __syncthreads();
#pragma unroll
        for (int j = 0; j < 16; j++) {
            int u = t + j * 256;
            int cr = u >> 6, dc = u & 63;
            g_WOth[(size_t)(c0 + cr) * DMODEL + d0 + dc] = __float2half_rn(tile[dc * 65 + cr]);
        }
    }
}

// ---------------------------------------------------------------------------
// proj_kernel: all three projections, fp16, BM=64 x BN=128 tiles, 2x4 warps ->
// warp 32x32, BK=64, 3-stage, single-sync, occupancy 3. z -> g_Qh/g_Kh/g_Vh.
// ---------------------------------------------------------------------------
__global__ __launch_bounds__(256, 3) void proj_kernel() {
    extern __shared__ float smf[];
    uint32_t sA = smem_u32(smf);           // [3][64 x 128B]  = 24KB
    uint32_t sB = sA + 3 * 8192;           // [3][128 x 128B] = 48KB

    int t = threadIdx.x, wid = t >> 5;
    int wm = wid & 1, wn = wid >> 1;       // 2x4 warps -> 64x128, warp 32x32
    int m0 = blockIdx.x * 64, n0 = blockIdx.y * 128, which = blockIdx.z;
    LANE_OFFS();

    const __half* A = g_Xh + (size_t)which * MROWS * DMODEL + (size_t)m0 * DMODEL;
    const __half* B = g_Wth + (size_t)which * DMODEL * DMODEL + (size_t)n0 * DMODEL;

    uint32_t aOffU = (uint32_t)(wm * 32 + aRow) * 128 + aK16;
    uint32_t bOffU = (uint32_t)(wn * 32 + bRow) * 128 + bK16;

    float acc[2][4][4];
#pragma unroll
    for (int mi = 0; mi < 2; mi++)
#pragma unroll
        for (int nj = 0; nj < 4; nj++)
#pragma unroll
            for (int e = 0; e < 4; e++) acc[mi][nj][e] = 0.0f;

    auto issue = [&](int it3) {
        int s = it3 % 3;
        int kk = it3 * 64;
        uint32_t bA = sA + s * 8192;
        uint32_t bB = sB + s * 16384;
#pragma unroll
        for (int j = 0; j < 2; j++) {          // A: 64 rows x 128B
            int u = t + j * 256;
            int row = u >> 3, ch = u & 7;
            cp16a(bA + swz(row * 128 + ch * 16), A + (size_t)row * DMODEL + kk + ch * 8);
        }
#pragma unroll
        for (int j = 0; j < 4; j++) {          // B: 128 rows x 128B
            int u = t + j * 256;
            int row = u >> 3, ch = u & 7;
            cp16a(bB + swz(row * 128 + ch * 16), B + (size_t)row * DMODEL + kk + ch * 8);
        }
    };

    issue(0); cp_commit();
    issue(1); cp_commit();
#pragma unroll 1
    for (int it = 0; it < 16; it++) {
        if (it < 15) cp_wait<1>(); else cp_wait<0>();
        __syncthreads();
        uint32_t bA = sA + (it % 3) * 8192;
        uint32_t bB = sB + (it % 3) * 16384;
#pragma unroll
        for (int slab = 0; slab < 4; slab++) {
            uint32_t a[2][4], b[2][4];
            ldsm4(a[0], bA + swz(aOffU + slab * 32));
            ldsm4(a[1], bA + swz(aOffU + 2048 + slab * 32));
            ldsm4(b[0], bB + swz(bOffU + slab * 32));
            ldsm4(b[1], bB + swz(bOffU + 2048 + slab * 32));
#pragma unroll
            for (int mi = 0; mi < 2; mi++)
#pragma unroll
                for (int nj = 0; nj < 4; nj++)
                    mma16h(acc[mi][nj], a[mi], &b[nj >> 1][(nj & 1) * 2]);
        }
        if (it + 2 < 16) { issue(it + 2); cp_commit(); }
    }

    __half* Outp = (which == 0) ? g_Qh : (which == 1) ? g_Kh : g_Vh;
#pragma unroll
    for (int mi = 0; mi < 2; mi++) {
        int mrow = m0 + wm * 32 + mi * 16 + gg;
#pragma unroll
        for (int nj = 0; nj < 4; nj++) {
            int col = n0 + wn * 32 + nj * 8 + 2 * tt;
            int b = mrow >> 11, s = mrow & (SEQ - 1);
            int h = col >> 6, e = col & 63;
            __half* dst = Outp + ((size_t)(b * NHEAD + h) * SEQ + s) * DHEAD + e;
            *(__half2*)dst = __floats2half2_rn(acc[mi][nj][0], acc[mi][nj][1]);
            *(__half2*)(dst + 8 * DHEAD) = __floats2half2_rn(acc[mi][nj][2], acc[mi][nj][3]);
        }
    }
}

// ---------------------------------------------------------------------------
// out_kernel (fp16, proj-style 64x128 tiles, BK=64, 3-stage, occupancy 3):
// Out = Ocat @ WOt^T -> fp32.
// ---------------------------------------------------------------------------
__global__ __launch_bounds__(256, 3) void out_kernel(float* __restrict__ Cout) {
    extern __shared__ float smf[];
    uint32_t sA = smem_u32(smf);           // [3][64 x 128B]  = 24KB
    uint32_t sB = sA + 3 * 8192;           // [3][128 x 128B] = 48KB

    int t = threadIdx.x, wid = t >> 5;
    int wm = wid & 1, wn = wid >> 1;       // 2x4 warps -> 64x128, warp 32x32
    int m0 = blockIdx.x * 64, n0 = blockIdx.y * 128;
    LANE_OFFS();

    const __half* A = g_Ocat + (size_t)m0 * DMODEL;
    const __half* B = g_WOth + (size_t)n0 * DMODEL;

    uint32_t aOffU = (uint32_t)(wm * 32 + aRow) * 128 + aK16;
    uint32_t bOffU = (uint32_t)(wn * 32 + bRow) * 128 + bK16;

    float acc[2][4][4];
#pragma unroll
    for (int mi = 0; mi < 2; mi++)
#pragma unroll
        for (int nj = 0; nj < 4; nj++)
#pragma unroll
            for (int e = 0; e < 4; e++) acc[mi][nj][e] = 0.0f;

    auto issue = [&](int it3) {
        int s = it3 % 3;
        int kk = it3 * 64;
        uint32_t bA = sA + s * 8192;
        uint32_t bB = sB + s * 16384;
#pragma unroll
        for (int j = 0; j < 2; j++) {
            int u = t + j * 256;
            int row = u >> 3, ch = u & 7;
            cp16a(bA + swz(row * 128 + ch * 16), A + (size_t)row * DMODEL + kk + ch * 8);
        }
#pragma unroll
        for (int j = 0; j < 4; j++) {
            int u = t + j * 256;
            int row = u >> 3, ch = u & 7;
            cp16a(bB + swz(row * 128 + ch * 16), B + (size_t)row * DMODEL + kk + ch * 8);
        }
    };

    issue(0); cp_commit();
    issue(1); cp_commit();
#pragma unroll 1
    for (int it = 0; it < 16; it++) {
        if (it < 15) cp_wait<1>(); else cp_wait<0>();
        __syncthreads();
        uint32_t bA = sA + (it % 3) * 8192;
        uint32_t bB = sB + (it % 3) * 16384;
#pragma unroll
        for (int slab = 0; slab < 4; slab++) {
            uint32_t a[2][4], b[2][4];
            ldsm4(a[0], bA + swz(aOffU + slab * 32));
            ldsm4(a[1], bA + swz(aOffU + 2048 + slab * 32));
            ldsm4(b[0], bB + swz(bOffU + slab * 32));
            ldsm4(b[1], bB + swz(bOffU + 2048 + slab * 32));
#pragma unroll
            for (int mi = 0; mi < 2; mi++)
#pragma unroll
                for (int nj = 0; nj < 4; nj++)
                    mma16h(acc[mi][nj], a[mi], &b[nj >> 1][(nj & 1) * 2]);
        }
        if (it + 2 < 16) { issue(it + 2); cp_commit(); }
    }

#pragma unroll
    for (int mi = 0; mi < 2; mi++) {
        int mrow = m0 + wm * 32 + mi * 16 + gg;
#pragma unroll
        for (int nj = 0; nj < 4; nj++) {
            int col = n0 + wn * 32 + nj * 8 + 2 * tt;
            float* d0 = Cout + (size_t)mrow * DMODEL + col;
            *(float2*)d0 = make_float2(acc[mi][nj][0], acc[mi][nj][1]);
            *(float2*)(d0 + 8 * DMODEL) = make_float2(acc[mi][nj][2], acc[mi][nj][3]);
        }
    }
}

// ---------------------------------------------------------------------------
// den_kernel (128q x 64k stripes): S = Q K^T; P = exp via PACKED f16x2
// epilogue (cvt pack -> HFMA2 -> ex2.f16x2), bias as packed half2 updated by
// HSUB2; masked (exact fp32) path only on iteration 0. P tile staged in smem
// and written as coalesced 128B rows. Colsums accumulated in fp32 from
// pairwise HADD2. fp16 V stripe scaled + transposed -> g_Vt.
// ---------------------------------------------------------------------------
#define PSTAGE_PITCH 72   // halves; 144B rows -> conflict-free half2 writes
__global__ __launch_bounds__(256, 2) void den_kernel() {
    int kt = blockIdx.x;          // kt=0 heaviest first
    int bh = blockIdx.y;

    extern __shared__ float smf[];
    uint32_t sK = smem_u32(smf);                 // fp16 K stripe: 8KB
    uint32_t sQ = sK + 8192;                     // fp16 Q tiles: 2 x 16KB
    __half* Pstage = (__half*)((char*)smf + 8192 + 32768);  // [128][72] fp16 = 18KB
    float* Vstage = (float*)Pstage;              // [64][65] fp32 (aliases, used at end)
    __shared__ float colsum[4][64];
    __shared__ float invs[64];

    int t = threadIdx.x, wid = t >> 5;
    int wm = wid & 3, wn = wid >> 2;             // 4x2 warps -> 128q x 64k
    LANE_OFFS();

    const __half* Qg = g_Qh + (size_t)bh * SEQ * DHEAD;
    const __half* Kg = g_Kh + ((size_t)bh * SEQ + kt * 64) * DHEAD;
    __half* Pb = g_Ph + (size_t)bh * SEQ * SEQ + kt * 64;

    auto issueQ = [&](int qt, int s) {
        const __half* src = Qg + (size_t)qt * 128 * DHEAD;
        uint32_t base = sQ + s * 16384;
#pragma unroll
        for (int j = 0; j < 4; j++) {
            int u = t + j * 256;
            int row = u >> 3, ch = u & 7;
            cp16a(base + swz(row * 128 + ch * 16), src + (size_t)row * DHEAD + ch * 8);
        }
    };

#pragma unroll
    for (int j = 0; j < 2; j++) {
        int u = t + j * 256;
        int row = u >> 3, ch = u & 7;
        cp16a(sK + swz(row * 128 + ch * 16), Kg + (size_t)row * DHEAD + ch * 8);
    }
    int qt0 = kt >> 1;
    issueQ(qt0, 0); cp_commit(); cp_wait<0>(); __syncthreads();

    uint32_t aOffU = (uint32_t)(wm * 32 + aRow) * 128 + aK16;
    uint32_t bOffU = (uint32_t)(wn * 32 + bRow) * 128 + bK16;

    // fp32 log2-domain constants for masked iteration 0
    float cb[4][2];
#pragma unroll
    for (int nj = 0; nj < 4; nj++) {
        int kg = kt * 64 + wn * 32 + nj * 8 + 2 * tt;
        cb[nj][0] = (float)kg * S2LOG;
        cb[nj][1] = (float)(kg + 1) * S2LOG;
    }
    float qv0[2][2];
#pragma unroll
    for (int mi = 0; mi < 2; mi++)
#pragma unroll
        for (int rh = 0; rh < 2; rh++)
            qv0[mi][rh] = (float)(qt0 * 128 + wm * 32 + mi * 16 + gg + rh * 8) * S2LOG;

    // packed half2 bias: hb[mi][nj][rh] = ((kg,kg+1) - q_row)*S2LOG
    const __half2 S2H = __float2half2_rn(S2LOG);
    const __half2 QSTEPH = __float2half2_rn(128.0f * S2LOG);
    __half2 hb[2][4][2];
#pragma unroll
    for (int mi = 0; mi < 2; mi++)
#pragma unroll
        for (int nj = 0; nj < 4; nj++)
#pragma unroll
            for (int rh = 0; rh < 2; rh++)
                hb[mi][nj][rh] = __floats2half2_rn(cb[nj][0] - qv0[mi][rh],
                                                   cb[nj][1] - qv0[mi][rh]);

    float part[4][2];
#pragma unroll
    for (int nj = 0; nj < 4; nj++) { part[nj][0] = 0.0f; part[nj][1] = 0.0f; }

#pragma unroll 1
    for (int qt = qt0; qt < SEQ / 128; qt++) {
        int it = qt - qt0;
        if (qt + 1 < SEQ / 128) { issueQ(qt + 1, (it + 1) & 1); cp_commit(); }

        uint32_t baQ = sQ + (it & 1) * 16384;
        float acc[2][4][4];
#pragma unroll
        for (int mi = 0; mi < 2; mi++)
#pragma unroll
            for (int nj = 0; nj < 4; nj++)
#pragma unroll
                for (int e = 0; e < 4; e++) acc[mi][nj][e] = 0.0f;

#pragma unroll
        for (int slab = 0; slab < 4; slab++) {
            uint32_t a[2][4], b[2][4];
            ldsm4(a[0], baQ + swz(aOffU + slab * 32));
            ldsm4(a[1], baQ + swz(aOffU + 2048 + slab * 32));
            ldsm4(b[0], sK + swz(bOffU + slab * 32));
            ldsm4(b[1], sK + swz(bOffU + 2048 + slab * 32));
#pragma unroll
            for (int mi = 0; mi < 2; mi++)
#pragma unroll
                for (int nj = 0; nj < 4; nj++)
                    mma16h(acc[mi][nj], a[mi], &b[nj >> 1][(nj & 1) * 2]);
        }

        if (it == 0) {
            // masked epilogue: exact fp32 + integer compares (only masked iter)
#pragma unroll
            for (int mi = 0; mi < 2; mi++) {
                int row = wm * 32 + mi * 16 + gg;
                int q = qt * 128 + row;
#pragma unroll
                for (int nj = 0; nj < 4; nj++) {
                    int kl = wn * 32 + nj * 8 + 2 * tt;
                    int kg = kt * 64 + kl;
                    float v0 = (kg     <= q) ? ex2f(fmaf(acc[mi][nj][0], S2LOG, cb[nj][0]) - qv0[mi][0]) : 0.0f;
                    float v1 = (kg + 1 <= q) ? ex2f(fmaf(acc[mi][nj][1], S2LOG, cb[nj][1]) - qv0[mi][0]) : 0.0f;
                    float v2 = (kg     <= q + 8) ? ex2f(fmaf(acc[mi][nj][2], S2LOG, cb[nj][0]) - qv0[mi][1]) : 0.0f;
                    float v3 = (kg + 1 <= q + 8) ? ex2f(fmaf(acc[mi][nj][3], S2LOG, cb[nj][1]) - qv0[mi][1]) : 0.0f;
                    part[nj][0] += v0 + v2;
                    part[nj][1] += v1 + v3;
                    *(__half2*)&Pstage[row * PSTAGE_PITCH + kl] = __floats2half2_rn(v0, v1);
                    *(__half2*)&Pstage[(row + 8) * PSTAGE_PITCH + kl] = __floats2half2_rn(v2, v3);
                }
            }
        } else {
            // packed f16x2 epilogue (mask-free region)
#pragma unroll
            for (int mi = 0; mi < 2; mi++) {
                int row = wm * 32 + mi * 16 + gg;
#pragma unroll
                for (int nj = 0; nj < 4; nj++) {
                    int kl = wn * 32 + nj * 8 + 2 * tt;
                    __half2 x0 = __floats2half2_rn(acc[mi][nj][0], acc[mi][nj][1]);
                    __half2 x1 = __floats2half2_rn(acc[mi][nj][2], acc[mi][nj][3]);
                    __half2 e0 = h2ex2(__hfma2(x0, S2H, hb[mi][nj][0]));
                    __half2 e1 = h2ex2(__hfma2(x1, S2H, hb[mi][nj][1]));
                    *(__half2*)&Pstage[row * PSTAGE_PITCH + kl] = e0;
                    *(__half2*)&Pstage[(row + 8) * PSTAGE_PITCH + kl] = e1;
                    __half2 s = __hadd2(e0, e1);   // (v0+v2, v1+v3), each <= 2
                    part[nj][0] += __low2float(s);
                    part[nj][1] += __high2float(s);
                }
            }
        }
        // advance packed bias by one 128-row q step
#pragma unroll
        for (int mi = 0; mi < 2; mi++)
#pragma unroll
            for (int nj = 0; nj < 4; nj++)
#pragma unroll
                for (int rh = 0; rh < 2; rh++)
                    hb[mi][nj][rh] = __hsub2(hb[mi][nj][rh], QSTEPH);

        __syncthreads();                      // Pstage fully written

        // coalesced P write-out: 128 rows x 128B, STG.128 full lines
        {
            int q0 = qt * 128;
#pragma unroll
            for (int j = 0; j < 4; j++) {
                int c = t + j * 256;          // 1024 chunks of 16B
                int row = c >> 3, seg = c & 7;
                uint4 v = *(const uint4*)&Pstage[row * PSTAGE_PITCH + seg * 8];
                *(uint4*)&Pb[(size_t)(q0 + row) * SEQ + seg * 8] = v;
            }
        }
        cp_wait<0>(); __syncthreads();        // next Q ready; Pstage reusable
    }

#pragma unroll
    for (int nj = 0; nj < 4; nj++)
#pragma unroll
        for (int p = 0; p < 2; p++) {
            float v = part[nj][p];
            v += __shfl_xor_sync(0xffffffffu, v, 4);
            v += __shfl_xor_sync(0xffffffffu, v, 8);
            v += __shfl_xor_sync(0xffffffffu, v, 16);
            part[nj][p] = v;
        }
    if (lane < 4) {
#pragma unroll
        for (int nj = 0; nj < 4; nj++) {
            colsum[wm][wn * 32 + nj * 8 + 2 * lane]     = part[nj][0];
            colsum[wm][wn * 32 + nj * 8 + 2 * lane + 1] = part[nj][1];
        }
    }
    __syncthreads();
    if (t < 64)
        invs[t] = 1.0f / (colsum[0][t] + colsum[1][t] + colsum[2][t] + colsum[3][t]);
    __syncthreads();

    // scale + transpose fp16 V stripe -> g_Vt (Vstage aliases Pstage; pitch 65)
    const __half* Vg = g_Vh + ((size_t)bh * SEQ + kt * 64) * DHEAD;
#pragma unroll
    for (int j = 0; j < 2; j++) {
        int u = t + j * 256;                 // 512 x 16B covers 64x64 halves
        int r = u >> 3, e8 = (u & 7) * 8;
        uint4 raw = *(const uint4*)&Vg[(size_t)r * DHEAD + e8];
        float iv = invs[r];
        __half2 h0 = *(__half2*)&raw.x, h1 = *(__half2*)&raw.y;
        __half2 h2 = *(__half2*)&raw.z, h3 = *(__half2*)&raw.w;
        Vstage[r * 65 + e8 + 0] = __low2float(h0) * iv;
        Vstage[r * 65 + e8 + 1] = __high2float(h0) * iv;
        Vstage[r * 65 + e8 + 2] = __low2float(h1) * iv;
        Vstage[r * 65 + e8 + 3] = __high2float(h1) * iv;
        Vstage[r * 65 + e8 + 4] = __low2float(h2) * iv;
        Vstage[r * 65 + e8 + 5] = __high2float(h2) * iv;
        Vstage[r * 65 + e8 + 6] = __low2float(h3) * iv;
        Vstage[r * 65 + e8 + 7] = __high2float(h3) * iv;
    }
    __syncthreads();
    __half* Vt = g_Vt + (size_t)bh * DHEAD * SEQ + kt * 64;
#pragma unroll
    for (int er = 0; er < 8; er++) {
        int e = wid * 8 + er;
#pragma unroll
        for (int half_ = 0; half_ < 2; half_++) {
            int r = lane + half_ * 32;
            Vt[(size_t)e * SEQ + r] = __float2half_rn(Vstage[r * 65 + e]);
        }
    }
}

// ---------------------------------------------------------------------------
// pv_kernel (fp16): Ocat[128q x 64e] = P @ Vt^T, BK=64, 3-stage, occupancy 3.
// bh processed in REVERSE (L2 temporal locality with den's write order).
// ---------------------------------------------------------------------------
__global__ __launch_bounds__(256, 3) void pv_kernel() {
    int qt = (int)gridDim.x - 1 - blockIdx.x;
    int bh = (int)gridDim.y - 1 - blockIdx.y;
    int b = bh >> 4, h = bh & 15;

    extern __shared__ float smf[];
    uint32_t sP = smem_u32(smf);                 // [3][128 x 128B] = 48KB
    uint32_t sV = sP + 3 * 16384;                // [3][64 x 128B]  = 24KB

    int t = threadIdx.x, wid = t >> 5;
    int wm = wid & 3, wn = wid >> 2;
    LANE_OFFS();

    const __half* Pg = g_Ph + ((size_t)bh * SEQ + qt * 128) * SEQ;
    const __half* Vtg = g_Vt + (size_t)bh * DHEAD * SEQ;

    float acc[2][4][4];
#pragma unroll
    for (int mi = 0; mi < 2; mi++)
#pragma unroll
        for (int nj = 0; nj < 4; nj++)
#pragma unroll
            for (int e = 0; e < 4; e++) acc[mi][nj][e] = 0.0f;

    int niter = 2 * qt + 2;

    auto issue = [&](int it3) {
        int s = it3 % 3;
        uint32_t bP = sP + s * 16384;
#pragma unroll
        for (int j = 0; j < 4; j++) {
            int u = t + j * 256;
            int row = u >> 3, ch = u & 7;
            cp16a(bP + swz(row * 128 + ch * 16), Pg + (size_t)row * SEQ + it3 * 64 + ch * 8);
        }
        uint32_t bV = sV + s * 8192;
#pragma unroll
        for (int j = 0; j < 2; j++) {
            int u = t + j * 256;
            int row = u >> 3, ch = u & 7;
            cp16a(bV + swz(row * 128 + ch * 16), Vtg + (size_t)row * SEQ + it3 * 64 + ch * 8);
        }
    };

    uint32_t aOffU = (uint32_t)(wm * 32 + aRow) * 128 + aK16;
    uint32_t bOffU = (uint32_t)(wn * 32 + bRow) * 128 + bK16;

    issue(0); cp_commit();
    if (niter > 1) { issue(1); cp_commit(); }
#pragma unroll 1
    for (int it = 0; it < niter; it++) {
        if (it + 1 < niter) cp_wait<1>(); else cp_wait<0>();
        __syncthreads();
        uint32_t bP = sP + (it % 3) * 16384;
        uint32_t bV = sV + (it % 3) * 8192;
#pragma unroll
        for (int slab = 0; slab < 4; slab++) {
            uint32_t a[2][4], bfr[2][4];
            ldsm4(a[0], bP + swz(aOffU + slab * 32));
            ldsm4(a[1], bP + swz(aOffU + 2048 + slab * 32));
            ldsm4(bfr[0], bV + swz(bOffU + slab * 32));
            ldsm4(bfr[1], bV + swz(bOffU + 2048 + slab * 32));
#pragma unroll
            for (int mi = 0; mi < 2; mi++)
#pragma unroll
                for (int nj = 0; nj < 4; nj++)
                    mma16h(acc[mi][nj], a[mi], &bfr[nj >> 1][(nj & 1) * 2]);
        }
        if (it + 2 < niter) { issue(it + 2); cp_commit(); }
    }

#pragma unroll
    for (int mi = 0; mi < 2; mi++) {
        int row = qt * 128 + wm * 32 + mi * 16 + gg;
#pragma unroll
        for (int nj = 0; nj < 4; nj++) {
            int colL = wn * 32 + nj * 8 + 2 * tt;
            __half* d0 = g_Ocat + ((size_t)(b * SEQ) + row) * DMODEL + h * 64 + colL;
            *(__half2*)d0 = __floats2half2_rn(acc[mi][nj][0], acc[mi][nj][1]);
            *(__half2*)(d0 + 8 * DMODEL) = __floats2half2_rn(acc[mi][nj][2], acc[mi][nj][3]);
        }
    }
}

// ---------------------------------------------------------------------------
// Launch. Inputs: keys, queries, values, WQ, WK, WV, WO, masking
// ---------------------------------------------------------------------------
extern "C" void kernel_launch(void* const* d_in, const int* in_sizes, int n_in,
                              void* d_out, int out_size) {
    const float* keys    = (const float*)d_in[0];
    const float* queries = (const float*)d_in[1];
    const float* values  = (const float*)d_in[2];
    const float* WQ      = (const float*)d_in[3];
    const float* WK      = (const float*)d_in[4];
    const float* WV      = (const float*)d_in[5];
    const float* WO      = (const float*)d_in[6];
    float* out = (float*)d_out;
    (void)in_sizes; (void)n_in; (void)out_size;

    const int projSmem = 3 * 8192 + 3 * 16384;                     // 73728
    const int outSmem  = 3 * 8192 + 3 * 16384;                     // 73728
    const int denSmem  = 8192 + 2 * 16384 + 128 * PSTAGE_PITCH * 2; // 59392
    const int pvSmem   = 3 * 16384 + 3 * 8192;                     // 73728
    cudaFuncSetAttribute(proj_kernel, cudaFuncAttributeMaxDynamicSharedMemorySize, projSmem);
    cudaFuncSetAttribute(out_kernel,  cudaFuncAttributeMaxDynamicSharedMemorySize, outSmem);
    cudaFuncSetAttribute(den_kernel,  cudaFuncAttributeMaxDynamicSharedMemorySize, denSmem);
    cudaFuncSetAttribute(pv_kernel,   cudaFuncAttributeMaxDynamicSharedMemorySize, pvSmem);

    // prologue (all fp16)
    xprep_kernel<<<dim3(MROWS * DMODEL / 4 / 256, 1, 3), 256>>>(
        (const float4*)queries, (const float4*)keys, (const float4*)values);
    wprep_kernel<<<dim3(DMODEL / 64, 16, 4), 256>>>(WQ, WK, WV, WO);

    // projections (z=0 Q, z=1 K, z=2 V)
    proj_kernel<<<dim3(MROWS / 64, DMODEL / 128, 3), 256, projSmem>>>();

    // attention (fp16)
    den_kernel<<<dim3(SEQ / 64, BH), 256, denSmem>>>();
    pv_kernel<<<dim3(SEQ / 128, BH), 256, pvSmem>>>();

    // output projection (fp16)
    out_kernel<<<dim3(MROWS / 64, DMODEL / 128), 256, outSmem>>>(out);
}